// round 5
// baseline (speedup 1.0000x reference)
#include <cuda_runtime.h>
#include <math.h>
#include <stdint.h>

#define B_ 4
#define S_ 2048
#define E_ 1024
#define MQ (B_*S_)

#define INV254  (1.f/254.f)

// ---------------- device scratch (allocation-free) ----------------
__device__ int8_t g_xq1[(size_t)MQ*E_],  g_xq2[(size_t)MQ*E_];
__device__ float  g_xs[MQ];
__device__ int8_t g_wq1[3][(size_t)E_*E_], g_wq2[3][(size_t)E_*E_];
__device__ float  g_ws[3][E_];
__device__ float  g_Qf[(size_t)MQ*E_], g_Kf[(size_t)MQ*E_];
__device__ float  g_Vf[(size_t)B_*E_*S_];                 // V^T fp32 [B][E][S]
__device__ int8_t g_Qq1[(size_t)MQ*E_], g_Qq2[(size_t)MQ*E_];
__device__ int8_t g_Kq1[(size_t)MQ*E_], g_Kq2[(size_t)MQ*E_];
__device__ int8_t g_Vq1[(size_t)B_*E_*S_], g_Vq2[(size_t)B_*E_*S_];
__device__ float  g_Qs[MQ], g_Ks[MQ], g_Vs[B_*E_];
__device__ float  g_P[(size_t)B_*S_*S_];
__device__ int8_t g_Pq1[(size_t)B_*S_*S_], g_Pq2[(size_t)B_*S_*S_];
__device__ float  g_Ps[B_*S_];

// ---------------- helpers ----------------
__device__ __forceinline__ uint32_t smem_u32(const void* p) {
    uint32_t a;
    asm("{ .reg .u64 t; cvta.to.shared.u64 t, %1; cvt.u32.u64 %0, t; }" : "=r"(a) : "l"(p));
    return a;
}
__device__ __forceinline__ void cp16(uint32_t s, const void* g) {
    asm volatile("cp.async.cg.shared.global [%0], [%1], 16;" :: "r"(s), "l"(g) : "memory");
}
#define CP_COMMIT() asm volatile("cp.async.commit_group;" ::: "memory")
#define CP_WAIT1()  asm volatile("cp.async.wait_group 1;" ::: "memory")
#define CP_WAIT0()  asm volatile("cp.async.wait_group 0;" ::: "memory")

__device__ __forceinline__ void ldsm4(uint32_t& r0, uint32_t& r1, uint32_t& r2, uint32_t& r3, uint32_t a) {
    asm volatile("ldmatrix.sync.aligned.m8n8.x4.shared.b16 {%0,%1,%2,%3}, [%4];"
                 : "=r"(r0), "=r"(r1), "=r"(r2), "=r"(r3) : "r"(a));
}
// s8 x s8 -> s32, m16n8k32
__device__ __forceinline__ void imma(int* c, const uint32_t* a, const uint32_t* b) {
    asm volatile("mma.sync.aligned.m16n8k32.row.col.s32.s8.s8.s32 "
                 "{%0,%1,%2,%3}, {%4,%5,%6,%7}, {%8,%9}, {%0,%1,%2,%3};"
                 : "+r"(c[0]), "+r"(c[1]), "+r"(c[2]), "+r"(c[3])
                 : "r"(a[0]), "r"(a[1]), "r"(a[2]), "r"(a[3]), "r"(b[0]), "r"(b[1]));
}

__device__ __forceinline__ uint32_t pack4(int a, int b, int c, int d) {
    return (uint32_t)(a & 0xFF) | ((uint32_t)(b & 0xFF) << 8) |
           ((uint32_t)(c & 0xFF) << 16) | ((uint32_t)(d & 0xFF) << 24);
}

// ---------------- int8 2-word GEMM ----------------
// D[m,n] = alpha * sA[m]*sB[n]*(P1 + P2/254 + P3/254^2) (+ bias[n])
// A,B K-major int8 word pairs (NT). modes: 0 = fp32 row-major; 1 = fp32 transposed [b][e][s].
#define MT2 128
#define NT2 64
#define KT2 32
#define PITCH 48
#define OFF_A2 6144
#define OFF_B1 12288
#define OFF_B2 15360
#define STG2  18432
#define SMEM2 (3*STG2)   // 55296 B

__global__ __launch_bounds__(256, 1)
void gemm_i8(const int8_t* __restrict__ A1, const int8_t* __restrict__ A2, const float* __restrict__ sA,
             const int8_t* __restrict__ B1, const int8_t* __restrict__ B2, const float* __restrict__ sB,
             const float* __restrict__ bias, float* __restrict__ out,
             int Ndim, int Kdim, float alpha,
             long aRows, long bRows, long cOff, int mode)
{
    extern __shared__ char smem[];
    const uint32_t sb = smem_u32(smem);
    const int tid = threadIdx.x, lane = tid & 31, wid = tid >> 5;
    const int wm = (wid & 3) * 32, wn = (wid >> 2) * 32;
    const long z = blockIdx.z;
    A1 += z * aRows * Kdim; A2 += z * aRows * Kdim; sA += z * aRows;
    B1 += z * bRows * Kdim; B2 += z * bRows * Kdim; sB += z * bRows;
    out += z * cOff;
    const int m0 = blockIdx.y * MT2, n0 = blockIdx.x * NT2;
    const int kt = Kdim / KT2;

    // loader: 3 x cp.async(16B) per thread per tile
    const int arow = tid >> 1, ahalf = tid & 1;
    const int bt = tid & 127, brow = bt >> 1, bhalf = bt & 1;
    const uint32_t aDst = arow * PITCH + ahalf * 16;
    const uint32_t bDst = OFF_B1 + ((tid >> 7) ? 3072u : 0u) + brow * PITCH + bhalf * 16;
    const int8_t* bSel = (tid < 128) ? B1 : B2;
    const long aSrc = (long)(m0 + arow) * Kdim + ahalf * 16;
    const long bSrc = (long)(n0 + brow) * Kdim + bhalf * 16;

    auto load_tile = [&](int it, int stg) {
        const uint32_t st = sb + stg * STG2;
        const long k0 = (long)it * KT2;
        cp16(st + aDst,          A1 + aSrc + k0);
        cp16(st + OFF_A2 + aDst, A2 + aSrc + k0);
        cp16(st + bDst,          bSel + bSrc + k0);
    };

    // ldmatrix lane offsets (int8 rows of 32B, pitch 48B)
    const uint32_t aoff = (wm + (lane & 7) + ((lane >> 3) & 1) * 8) * PITCH + (lane >> 4) * 16;
    const uint32_t boff = (wn + (lane & 7) + (lane >> 4) * 8) * PITCH + ((lane >> 3) & 1) * 16;

    int c1[2][4][4], c2[2][4][4], c3[2][4][4];
    #pragma unroll
    for (int i = 0; i < 2; i++)
        #pragma unroll
        for (int j = 0; j < 4; j++)
            #pragma unroll
            for (int q = 0; q < 4; q++) { c1[i][j][q] = 0; c2[i][j][q] = 0; c3[i][j][q] = 0; }

    load_tile(0, 0); CP_COMMIT();
    load_tile(1, 1); CP_COMMIT();

    for (int it = 0; it < kt; it++) {
        CP_WAIT1();
        __syncthreads();
        if (it + 2 < kt) load_tile(it + 2, (it + 2) % 3);
        CP_COMMIT();

        const uint32_t st = sb + (it % 3) * STG2;
        uint32_t a1f[2][4], a2f[2][4], b1f[4][2], b2f[4][2];
        #pragma unroll
        for (int i = 0; i < 2; i++) {
            ldsm4(a1f[i][0], a1f[i][1], a1f[i][2], a1f[i][3], st + aoff + i * 16 * PITCH);
            ldsm4(a2f[i][0], a2f[i][1], a2f[i][2], a2f[i][3], st + OFF_A2 + aoff + i * 16 * PITCH);
        }
        #pragma unroll
        for (int g = 0; g < 2; g++) {
            uint32_t r0, r1, r2, r3;
            ldsm4(r0, r1, r2, r3, st + OFF_B1 + boff + g * 16 * PITCH);
            b1f[2 * g][0] = r0; b1f[2 * g][1] = r1; b1f[2 * g + 1][0] = r2; b1f[2 * g + 1][1] = r3;
            ldsm4(r0, r1, r2, r3, st + OFF_B2 + boff + g * 16 * PITCH);
            b2f[2 * g][0] = r0; b2f[2 * g][1] = r1; b2f[2 * g + 1][0] = r2; b2f[2 * g + 1][1] = r3;
        }
        #pragma unroll
        for (int i = 0; i < 2; i++)
            #pragma unroll
            for (int j = 0; j < 4; j++) imma(c1[i][j], a1f[i], b1f[j]);
        #pragma unroll
        for (int i = 0; i < 2; i++)
            #pragma unroll
            for (int j = 0; j < 4; j++) imma(c2[i][j], a1f[i], b2f[j]);
        #pragma unroll
        for (int i = 0; i < 2; i++)
            #pragma unroll
            for (int j = 0; j < 4; j++) imma(c2[i][j], a2f[i], b1f[j]);
        #pragma unroll
        for (int i = 0; i < 2; i++)
            #pragma unroll
            for (int j = 0; j < 4; j++) imma(c3[i][j], a2f[i], b2f[j]);
    }
    CP_WAIT0();
    __syncthreads();

    // ---------------- epilogue ----------------
    const int r = lane >> 2, cq = (lane & 3) * 2;

    if (mode == 1) {
        float* ep = reinterpret_cast<float*>(smem);       // 128 x 68 fp32
        #pragma unroll
        for (int i = 0; i < 2; i++)
            #pragma unroll
            for (int j = 0; j < 4; j++) {
                const int cl = wn + j * 8 + cq;
                const float s0 = sB[n0 + cl], s1 = sB[n0 + cl + 1];
                const float b0 = bias ? bias[n0 + cl] : 0.f;
                const float b1 = bias ? bias[n0 + cl + 1] : 0.f;
                #pragma unroll
                for (int h = 0; h < 2; h++) {
                    const int row = wm + i * 16 + r + h * 8;
                    const float sa = sA[m0 + row] * alpha;
                    float v0 = sa * s0 * ((float)c1[i][j][2*h] + (float)c2[i][j][2*h] * INV254
                                          + (float)c3[i][j][2*h] * (INV254 * INV254)) + b0;
                    float v1 = sa * s1 * ((float)c1[i][j][2*h+1] + (float)c2[i][j][2*h+1] * INV254
                                          + (float)c3[i][j][2*h+1] * (INV254 * INV254)) + b1;
                    ep[row * 68 + cl] = v0;
                    ep[row * 68 + cl + 1] = v1;
                }
            }
        __syncthreads();
        const int c = tid >> 2, part = tid & 3;
        const long bidx = (long)(m0 >> 11);
        const int s0i = (m0 & 2047) + part * 32;
        const long base = bidx * E_ * S_ + (long)(n0 + c) * S_ + s0i;
        #pragma unroll
        for (int k = 0; k < 32; k += 4) {
            float4 v;
            v.x = ep[(part * 32 + k + 0) * 68 + c];
            v.y = ep[(part * 32 + k + 1) * 68 + c];
            v.z = ep[(part * 32 + k + 2) * 68 + c];
            v.w = ep[(part * 32 + k + 3) * 68 + c];
            *reinterpret_cast<float4*>(out + base + k) = v;
        }
        return;
    }

    #pragma unroll
    for (int i = 0; i < 2; i++)
        #pragma unroll
        for (int j = 0; j < 4; j++) {
            const int gn = n0 + wn + j * 8 + cq;
            const float s0 = sB[gn], s1 = sB[gn + 1];
            const float b0 = bias ? bias[gn] : 0.f;
            const float b1 = bias ? bias[gn + 1] : 0.f;
            #pragma unroll
            for (int h = 0; h < 2; h++) {
                const long gm = m0 + wm + i * 16 + r + h * 8;
                const float sa = sA[gm] * alpha;
                float v0 = sa * s0 * ((float)c1[i][j][2*h] + (float)c2[i][j][2*h] * INV254
                                      + (float)c3[i][j][2*h] * (INV254 * INV254)) + b0;
                float v1 = sa * s1 * ((float)c1[i][j][2*h+1] + (float)c2[i][j][2*h+1] * INV254
                                      + (float)c3[i][j][2*h+1] * (INV254 * INV254)) + b1;
                *reinterpret_cast<float2*>(out + gm * Ndim + gn) = make_float2(v0, v1);
            }
        }
}

// ---------------- per-row 2-word int8 quantization ----------------
// x = s*(a1 + a2/254), s = rowmax/127
__global__ __launch_bounds__(256)
void quant_rows(const float* __restrict__ src, int8_t* __restrict__ q1,
                int8_t* __restrict__ q2, float* __restrict__ scale, int cols)
{
    const long row = blockIdx.x;
    const float* p = src + row * (long)cols;
    const int tid = threadIdx.x;
    const int vpt = cols >> 8;                  // 4 or 8

    float v[8];
    float mx = 0.f;
    #pragma unroll 2
    for (int c = 0; c < vpt; c += 4) {
        float4 t = *reinterpret_cast<const float4*>(p + tid * vpt + c);
        v[c] = t.x; v[c+1] = t.y; v[c+2] = t.z; v[c+3] = t.w;
        mx = fmaxf(mx, fmaxf(fmaxf(fabsf(t.x), fabsf(t.y)), fmaxf(fabsf(t.z), fabsf(t.w))));
    }
    __shared__ float red[8];
    #pragma unroll
    for (int o = 16; o > 0; o >>= 1) mx = fmaxf(mx, __shfl_xor_sync(0xffffffffu, mx, o));
    if ((tid & 31) == 0) red[tid >> 5] = mx;
    __syncthreads();
    float m = red[0];
    #pragma unroll
    for (int i = 1; i < 8; i++) m = fmaxf(m, red[i]);
    if (m < 1e-30f) m = 1e-30f;
    const float inv = 127.f / m;
    if (tid == 0) scale[row] = m * (1.f / 127.f);

    #pragma unroll 2
    for (int c = 0; c < vpt; c += 4) {
        int a1[4], a2[4];
        #pragma unroll
        for (int k = 0; k < 4; k++) {
            float q = v[c + k] * inv;
            float f1 = rintf(q);
            a1[k] = (int)f1;
            a2[k] = (int)rintf((q - f1) * 254.f);
        }
        uint32_t w1 = pack4(a1[0], a1[1], a1[2], a1[3]);
        uint32_t w2 = pack4(a2[0], a2[1], a2[2], a2[3]);
        *reinterpret_cast<uint32_t*>(q1 + row * (long)cols + tid * vpt + c) = w1;
        *reinterpret_cast<uint32_t*>(q2 + row * (long)cols + tid * vpt + c) = w2;
    }
}

// ---------------- softmax + per-row int8 quantization ----------------
// q_i = exp(z_i - zmax) in (0,1]; p_i = q_i/tot; scale = 1/(127*tot)
__global__ __launch_bounds__(256)
void softmax_quant(const float* __restrict__ P, int8_t* __restrict__ q1,
                   int8_t* __restrict__ q2, float* __restrict__ scale)
{
    const long row = blockIdx.x;
    const float* p = P + row * (long)S_;
    const int tid = threadIdx.x;

    float v[8];
    float mx = -INFINITY;
    #pragma unroll
    for (int c = 0; c < 8; c += 4) {
        float4 t = *reinterpret_cast<const float4*>(p + tid * 8 + c);
        v[c] = t.x; v[c+1] = t.y; v[c+2] = t.z; v[c+3] = t.w;
        mx = fmaxf(mx, fmaxf(fmaxf(t.x, t.y), fmaxf(t.z, t.w)));
    }
    __shared__ float red[8];
    #pragma unroll
    for (int o = 16; o > 0; o >>= 1) mx = fmaxf(mx, __shfl_xor_sync(0xffffffffu, mx, o));
    if ((tid & 31) == 0) red[tid >> 5] = mx;
    __syncthreads();
    float zm = red[0];
    #pragma unroll
    for (int i = 1; i < 8; i++) zm = fmaxf(zm, red[i]);
    __syncthreads();

    float sm = 0.f;
    #pragma unroll
    for (int i = 0; i < 8; i++) { v[i] = __expf(v[i] - zm); sm += v[i]; }
    #pragma unroll
    for (int o = 16; o > 0; o >>= 1) sm += __shfl_xor_sync(0xffffffffu, sm, o);
    if ((tid & 31) == 0) red[tid >> 5] = sm;
    __syncthreads();
    float tot = 0.f;
    #pragma unroll
    for (int i = 0; i < 8; i++) tot += red[i];
    if (tid == 0) scale[row] = 1.f / (127.f * tot);

    #pragma unroll
    for (int c = 0; c < 8; c += 4) {
        int a1[4], a2[4];
        #pragma unroll
        for (int k = 0; k < 4; k++) {
            float q = v[c + k] * 127.f;
            float f1 = rintf(q);
            a1[k] = (int)f1;
            a2[k] = (int)rintf((q - f1) * 254.f);
        }
        *reinterpret_cast<uint32_t*>(q1 + row * (long)S_ + tid * 8 + c) = pack4(a1[0], a1[1], a1[2], a1[3]);
        *reinterpret_cast<uint32_t*>(q2 + row * (long)S_ + tid * 8 + c) = pack4(a2[0], a2[1], a2[2], a2[3]);
    }
}

// ---------------- launch ----------------
extern "C" void kernel_launch(void* const* d_in, const int* in_sizes, int n_in,
                              void* d_out, int out_size)
{
    const float* x  = (const float*)d_in[0];
    const float* wq = (const float*)d_in[1];
    const float* bq = (const float*)d_in[2];
    const float* wk = (const float*)d_in[3];
    const float* bk = (const float*)d_in[4];
    const float* wv = (const float*)d_in[5];
    const float* bv = (const float*)d_in[6];
    float* out = (float*)d_out;

    int8_t *xq1, *xq2, *wq1, *wq2, *Qq1, *Qq2, *Kq1, *Kq2, *Vq1, *Vq2, *Pq1, *Pq2;
    float *xs, *ws, *Qf, *Kf, *Vf, *Qs, *Ks, *Vs, *P, *Ps;
    cudaGetSymbolAddress((void**)&xq1, g_xq1); cudaGetSymbolAddress((void**)&xq2, g_xq2);
    cudaGetSymbolAddress((void**)&xs, g_xs);
    cudaGetSymbolAddress((void**)&wq1, g_wq1); cudaGetSymbolAddress((void**)&wq2, g_wq2);
    cudaGetSymbolAddress((void**)&ws, g_ws);
    cudaGetSymbolAddress((void**)&Qf, g_Qf); cudaGetSymbolAddress((void**)&Kf, g_Kf);
    cudaGetSymbolAddress((void**)&Vf, g_Vf);
    cudaGetSymbolAddress((void**)&Qq1, g_Qq1); cudaGetSymbolAddress((void**)&Qq2, g_Qq2);
    cudaGetSymbolAddress((void**)&Kq1, g_Kq1); cudaGetSymbolAddress((void**)&Kq2, g_Kq2);
    cudaGetSymbolAddress((void**)&Vq1, g_Vq1); cudaGetSymbolAddress((void**)&Vq2, g_Vq2);
    cudaGetSymbolAddress((void**)&Qs, g_Qs); cudaGetSymbolAddress((void**)&Ks, g_Ks);
    cudaGetSymbolAddress((void**)&Vs, g_Vs);
    cudaGetSymbolAddress((void**)&P, g_P);
    cudaGetSymbolAddress((void**)&Pq1, g_Pq1); cudaGetSymbolAddress((void**)&Pq2, g_Pq2);
    cudaGetSymbolAddress((void**)&Ps, g_Ps);

    cudaFuncSetAttribute(gemm_i8, cudaFuncAttributeMaxDynamicSharedMemorySize, SMEM2);

    const long nw = (long)E_ * E_;

    // quantize inputs
    quant_rows<<<MQ, 256>>>(x, xq1, xq2, xs, E_);
    quant_rows<<<E_, 256>>>(wq, wq1 + 0 * nw, wq2 + 0 * nw, ws + 0 * E_, E_);
    quant_rows<<<E_, 256>>>(wk, wq1 + 1 * nw, wq2 + 1 * nw, ws + 1 * E_, E_);
    quant_rows<<<E_, 256>>>(wv, wq1 + 2 * nw, wq2 + 2 * nw, ws + 2 * E_, E_);

    // QKV projections: M=8192, N=1024, K=1024 -> fp32 (V transposed)
    dim3 g1(E_ / NT2, MQ / MT2, 1);
    gemm_i8<<<g1, 256, SMEM2>>>(xq1, xq2, xs, wq1 + 0 * nw, wq2 + 0 * nw, ws + 0 * E_,
                                bq, Qf, E_, E_, 1.f, 0, 0, 0, 0);
    gemm_i8<<<g1, 256, SMEM2>>>(xq1, xq2, xs, wq1 + 1 * nw, wq2 + 1 * nw, ws + 1 * E_,
                                bk, Kf, E_, E_, 1.f, 0, 0, 0, 0);
    gemm_i8<<<g1, 256, SMEM2>>>(xq1, xq2, xs, wq1 + 2 * nw, wq2 + 2 * nw, ws + 2 * E_,
                                bv, Vf, E_, E_, 1.f, 0, 0, 0, 1);

    // re-quantize Q, K (rows of 1024) and V^T (rows of 2048)
    quant_rows<<<MQ, 256>>>(Qf, Qq1, Qq2, Qs, E_);
    quant_rows<<<MQ, 256>>>(Kf, Kq1, Kq2, Ks, E_);
    quant_rows<<<B_ * E_, 256>>>(Vf, Vq1, Vq2, Vs, S_);

    // scores = Q K^T / 32, per batch: M=N=2048, K=1024
    dim3 g2(S_ / NT2, S_ / MT2, B_);
    gemm_i8<<<g2, 256, SMEM2>>>(Qq1, Qq2, Qs, Kq1, Kq2, Ks, nullptr, P,
                                S_, E_, 0.03125f, S_, S_, (long)S_ * S_, 0);

    // softmax + quantize P per row
    softmax_quant<<<B_ * S_, 256>>>(P, Pq1, Pq2, Ps);

    // out = P V, per batch: M=2048, N=1024, K=2048 (B = V^T)
    dim3 g3(E_ / NT2, S_ / MT2, B_);
    gemm_i8<<<g3, 256, SMEM2>>>(Pq1, Pq2, Ps, Vq1, Vq2, Vs, nullptr, out,
                                E_, S_, 1.f, S_, E_, (long)S_ * E_, 0);
}

// round 6
// speedup vs baseline: 4.0452x; 4.0452x over previous
#include <cuda_runtime.h>
#include <cuda_fp16.h>
#include <math.h>
#include <stdint.h>

#define B_ 4
#define S_ 2048
#define E_ 1024
#define MQ (B_*S_)

// ---------------- device scratch (allocation-free) ----------------
__device__ __half g_xh[(size_t)MQ*E_];
__device__ __half g_wh[3][(size_t)E_*E_], g_wl[3][(size_t)E_*E_];
__device__ __half g_Qh[(size_t)MQ*E_];                     // Q plain (A operand)
__device__ __half g_Kh[(size_t)MQ*E_], g_Kl[(size_t)MQ*E_];
__device__ __half g_Vh[(size_t)MQ*E_], g_Vl[(size_t)MQ*E_]; // V^T: [B][E][S]
__device__ float  g_P [(size_t)B_*S_*S_];
__device__ __half g_Ph[(size_t)B_*S_*S_];                  // P plain (A operand)

// ---------------- helpers ----------------
__device__ __forceinline__ uint32_t smem_u32(const void* p) {
    uint32_t a;
    asm("{ .reg .u64 t; cvta.to.shared.u64 t, %1; cvt.u32.u64 %0, t; }" : "=r"(a) : "l"(p));
    return a;
}
__device__ __forceinline__ void cp16(uint32_t s, const void* g) {
    asm volatile("cp.async.cg.shared.global [%0], [%1], 16;" :: "r"(s), "l"(g) : "memory");
}
#define CP_COMMIT() asm volatile("cp.async.commit_group;" ::: "memory")
#define CP_WAIT1()  asm volatile("cp.async.wait_group 1;" ::: "memory")
#define CP_WAIT0()  asm volatile("cp.async.wait_group 0;" ::: "memory")

__device__ __forceinline__ void ldsm4(uint32_t& r0, uint32_t& r1, uint32_t& r2, uint32_t& r3, uint32_t a) {
    asm volatile("ldmatrix.sync.aligned.m8n8.x4.shared.b16 {%0,%1,%2,%3}, [%4];"
                 : "=r"(r0), "=r"(r1), "=r"(r2), "=r"(r3) : "r"(a));
}
__device__ __forceinline__ void mma_f32(float* c, const uint32_t* a, const uint32_t* b) {
    asm volatile("mma.sync.aligned.m16n8k16.row.col.f32.f16.f16.f32 "
                 "{%0,%1,%2,%3}, {%4,%5,%6,%7}, {%8,%9}, {%0,%1,%2,%3};"
                 : "+f"(c[0]), "+f"(c[1]), "+f"(c[2]), "+f"(c[3])
                 : "r"(a[0]), "r"(a[1]), "r"(a[2]), "r"(a[3]), "r"(b[0]), "r"(b[1]));
}

// ---------------- asymmetric-split fp16 GEMM ----------------
// D[M,N] = alpha*(A @ (Bh+Bl)^T) (+ bias[n]);  A plain fp16, B split fp16.
// modes: 0 = fp16 plain row-major (Oh)
//        1 = fp16 split row-major (Oh,Ol)
//        2 = fp16 split transposed [b][n][s] (V path)
//        3 = fp32 row-major (Cf)
#define MT 128
#define NT 128
#define KT 32
#define NTH 256
#define NSTG 3
#define ARR_B (128*40*2)              // 128 rows * 80 B (32 elems + 8 pad)
#define STG_B (3*ARR_B)               // A, Bh, Bl = 30720 B
#define SMEM_SZ (NSTG*STG_B)          // 92160 B

__global__ __launch_bounds__(NTH, 1)
void gemm_asym(const __half* __restrict__ A, const __half* __restrict__ Bh,
               const __half* __restrict__ Bl, const float* __restrict__ bias,
               float* __restrict__ Cf, __half* __restrict__ Oh, __half* __restrict__ Ol,
               int Ndim, int Kdim, float alpha,
               long sA, long sB, long sC, int mode)
{
    extern __shared__ char smem[];
    const uint32_t sb = smem_u32(smem);
    const int tid = threadIdx.x, lane = tid & 31, wid = tid >> 5;
    const int wm = (wid >> 2) * 64;          // warp M offset (0,64)
    const int wn = (wid & 3) * 32;           // warp N offset (0,32,64,96)
    const long z = blockIdx.z;
    A += z * sA; Bh += z * sB; Bl += z * sB;
    const int m0 = blockIdx.y * MT, n0 = blockIdx.x * NT;
    const int kt = Kdim / KT;

    auto load_tile = [&](int it, int stage) {
        const uint32_t st = sb + stage * STG_B;
        const long k0 = (long)it * KT;
        #pragma unroll
        for (int arr = 0; arr < 3; arr++) {
            const __half* src = (arr == 0) ? A : (arr == 1) ? Bh : Bl;
            const int rbase = (arr == 0) ? m0 : n0;
            const uint32_t ab = st + arr * ARR_B;
            #pragma unroll
            for (int i = 0; i < 2; i++) {
                int c = tid + i * NTH;
                int row = c >> 2, kc = c & 3;
                cp16(ab + row * 80 + kc * 16,
                     src + (long)(rbase + row) * Kdim + k0 + kc * 8);
            }
        }
    };

    float acc[4][4][4];
    #pragma unroll
    for (int i = 0; i < 4; i++)
        #pragma unroll
        for (int j = 0; j < 4; j++)
            #pragma unroll
            for (int q = 0; q < 4; q++) acc[i][j][q] = 0.f;

    const uint32_t a_row = (lane & 15), a_k = (lane >> 4) * 8;
    const uint32_t b_n = ((lane >> 4) & 1) * 8 + (lane & 7), b_k = ((lane >> 3) & 1) * 8;

    load_tile(0, 0); CP_COMMIT();
    load_tile(1, 1); CP_COMMIT();

    for (int it = 0; it < kt; it++) {
        CP_WAIT1();
        __syncthreads();
        if (it + 2 < kt) load_tile(it + 2, (it + 2) % NSTG);
        CP_COMMIT();

        const uint32_t st = sb + (it % NSTG) * STG_B;
        #pragma unroll
        for (int ks = 0; ks < 2; ks++) {
            uint32_t ah[4][4], bh[4][2], bl[4][2];
            #pragma unroll
            for (int i = 0; i < 4; i++) {
                uint32_t off = (wm + i * 16 + a_row) * 80 + (ks * 16 + a_k) * 2;
                ldsm4(ah[i][0], ah[i][1], ah[i][2], ah[i][3], st + off);
            }
            #pragma unroll
            for (int jj = 0; jj < 2; jj++) {
                uint32_t off = (wn + jj * 16 + b_n) * 80 + (ks * 16 + b_k) * 2;
                uint32_t r0, r1, r2, r3;
                ldsm4(r0, r1, r2, r3, st + ARR_B + off);
                bh[2 * jj][0] = r0; bh[2 * jj][1] = r1; bh[2 * jj + 1][0] = r2; bh[2 * jj + 1][1] = r3;
                ldsm4(r0, r1, r2, r3, st + 2 * ARR_B + off);
                bl[2 * jj][0] = r0; bl[2 * jj][1] = r1; bl[2 * jj + 1][0] = r2; bl[2 * jj + 1][1] = r3;
            }
            #pragma unroll
            for (int i = 0; i < 4; i++)
                #pragma unroll
                for (int j = 0; j < 4; j++) mma_f32(acc[i][j], ah[i], bh[j]);
            #pragma unroll
            for (int i = 0; i < 4; i++)
                #pragma unroll
                for (int j = 0; j < 4; j++) mma_f32(acc[i][j], ah[i], bl[j]);
        }
    }
    CP_WAIT0();

    // ---------------- epilogue ----------------
    const int r = lane >> 2, cq = (lane & 3) * 2;

    if (mode == 2) {
        // stage hi/lo tiles in smem, then coalesced transposed store [b][n][s]
        __syncthreads();
        __half* sh = reinterpret_cast<__half*>(smem);
        __half* sl = sh + 128 * 136;
        #pragma unroll
        for (int i = 0; i < 4; i++)
            #pragma unroll
            for (int j = 0; j < 4; j++) {
                const int cl = wn + j * 8 + cq;
                #pragma unroll
                for (int h = 0; h < 2; h++) {
                    const int row = wm + i * 16 + r + h * 8;
                    float v0 = acc[i][j][2 * h + 0] * alpha;
                    float v1 = acc[i][j][2 * h + 1] * alpha;
                    if (bias) { v0 += __ldg(bias + n0 + cl); v1 += __ldg(bias + n0 + cl + 1); }
                    __half h0 = __float2half_rn(v0), h1 = __float2half_rn(v1);
                    sh[row * 136 + cl]     = h0;
                    sh[row * 136 + cl + 1] = h1;
                    sl[row * 136 + cl]     = __float2half_rn(v0 - __half2float(h0));
                    sl[row * 136 + cl + 1] = __float2half_rn(v1 - __half2float(h1));
                }
            }
        __syncthreads();
        const int c = tid >> 1, half_ = tid & 1;
        const long bidx = (long)(m0 >> 11);
        const int sbase = (m0 & 2047) + half_ * 64;
        const long obase = bidx * E_ * S_ + (long)(n0 + c) * S_ + sbase;
        #pragma unroll
        for (int mm = 0; mm < 64; mm += 8) {
            const int m = half_ * 64 + mm;
            unsigned short uh[8], ul[8];
            #pragma unroll
            for (int t = 0; t < 8; t++) {
                uh[t] = __half_as_ushort(sh[(m + t) * 136 + c]);
                ul[t] = __half_as_ushort(sl[(m + t) * 136 + c]);
            }
            *reinterpret_cast<ushort4*>(Oh + obase + mm)     = make_ushort4(uh[0], uh[1], uh[2], uh[3]);
            *reinterpret_cast<ushort4*>(Oh + obase + mm + 4) = make_ushort4(uh[4], uh[5], uh[6], uh[7]);
            *reinterpret_cast<ushort4*>(Ol + obase + mm)     = make_ushort4(ul[0], ul[1], ul[2], ul[3]);
            *reinterpret_cast<ushort4*>(Ol + obase + mm + 4) = make_ushort4(ul[4], ul[5], ul[6], ul[7]);
        }
        return;
    }

    #pragma unroll
    for (int i = 0; i < 4; i++)
        #pragma unroll
        for (int j = 0; j < 4; j++) {
            const int gn = n0 + wn + j * 8 + cq;
            float bv0 = 0.f, bv1 = 0.f;
            if (bias) { bv0 = __ldg(bias + gn); bv1 = __ldg(bias + gn + 1); }
            #pragma unroll
            for (int h = 0; h < 2; h++) {
                const long gm = m0 + wm + i * 16 + r + h * 8;
                float v0 = acc[i][j][2 * h + 0] * alpha + bv0;
                float v1 = acc[i][j][2 * h + 1] * alpha + bv1;
                if (mode == 3) {
                    *reinterpret_cast<float2*>(Cf + z * sC + gm * Ndim + gn) = make_float2(v0, v1);
                } else if (mode == 0) {
                    *reinterpret_cast<ushort2*>(Oh + gm * Ndim + gn) =
                        make_ushort2(__half_as_ushort(__float2half_rn(v0)),
                                     __half_as_ushort(__float2half_rn(v1)));
                } else {
                    __half h0 = __float2half_rn(v0), h1 = __float2half_rn(v1);
                    __half l0 = __float2half_rn(v0 - __half2float(h0));
                    __half l1 = __float2half_rn(v1 - __half2float(h1));
                    *reinterpret_cast<ushort2*>(Oh + gm * Ndim + gn) =
                        make_ushort2(__half_as_ushort(h0), __half_as_ushort(h1));
                    *reinterpret_cast<ushort2*>(Ol + gm * Ndim + gn) =
                        make_ushort2(__half_as_ushort(l0), __half_as_ushort(l1));
                }
            }
        }
}

// ---------------- fp32 -> fp16 plain ----------------
__global__ __launch_bounds__(256)
void conv_f16(const float* __restrict__ s, __half* __restrict__ h, long n)
{
    long i = ((long)blockIdx.x * blockDim.x + threadIdx.x) * 4;
    if (i >= n) return;
    float4 v = *reinterpret_cast<const float4*>(s + i);
    *reinterpret_cast<ushort4*>(h + i) = make_ushort4(
        __half_as_ushort(__float2half_rn(v.x)), __half_as_ushort(__float2half_rn(v.y)),
        __half_as_ushort(__float2half_rn(v.z)), __half_as_ushort(__float2half_rn(v.w)));
}

// ---------------- fp32 -> fp16 hi/lo split ----------------
__global__ __launch_bounds__(256)
void split_f16(const float* __restrict__ s, __half* __restrict__ h,
               __half* __restrict__ l, long n)
{
    long i = ((long)blockIdx.x * blockDim.x + threadIdx.x) * 4;
    if (i >= n) return;
    float4 v = *reinterpret_cast<const float4*>(s + i);
    float a[4] = {v.x, v.y, v.z, v.w};
    unsigned short hh[4], ll[4];
    #pragma unroll
    for (int k = 0; k < 4; k++) {
        __half hb = __float2half_rn(a[k]);
        __half lb = __float2half_rn(a[k] - __half2float(hb));
        hh[k] = __half_as_ushort(hb); ll[k] = __half_as_ushort(lb);
    }
    *reinterpret_cast<ushort4*>(h + i) = make_ushort4(hh[0], hh[1], hh[2], hh[3]);
    *reinterpret_cast<ushort4*>(l + i) = make_ushort4(ll[0], ll[1], ll[2], ll[3]);
}

// ---------------- softmax -> fp16 plain ----------------
__global__ __launch_bounds__(256)
void softmax_f16(const float* __restrict__ P, __half* __restrict__ Ph)
{
    const long row = blockIdx.x;
    const float* p = P + row * (long)S_;
    const int tid = threadIdx.x;

    float v[8];
    float mx = -INFINITY;
    #pragma unroll
    for (int c = 0; c < 8; c += 4) {
        float4 t = *reinterpret_cast<const float4*>(p + tid * 8 + c);
        v[c] = t.x; v[c+1] = t.y; v[c+2] = t.z; v[c+3] = t.w;
        mx = fmaxf(mx, fmaxf(fmaxf(t.x, t.y), fmaxf(t.z, t.w)));
    }
    __shared__ float red[8];
    #pragma unroll
    for (int o = 16; o > 0; o >>= 1) mx = fmaxf(mx, __shfl_xor_sync(0xffffffffu, mx, o));
    if ((tid & 31) == 0) red[tid >> 5] = mx;
    __syncthreads();
    float zm = red[0];
    #pragma unroll
    for (int i = 1; i < 8; i++) zm = fmaxf(zm, red[i]);
    __syncthreads();

    float sm = 0.f;
    #pragma unroll
    for (int i = 0; i < 8; i++) { v[i] = __expf(v[i] - zm); sm += v[i]; }
    #pragma unroll
    for (int o = 16; o > 0; o >>= 1) sm += __shfl_xor_sync(0xffffffffu, sm, o);
    if ((tid & 31) == 0) red[tid >> 5] = sm;
    __syncthreads();
    float tot = 0.f;
    #pragma unroll
    for (int i = 0; i < 8; i++) tot += red[i];
    const float inv = 1.f / tot;

    #pragma unroll
    for (int c = 0; c < 8; c += 4) {
        ushort4 o;
        o.x = __half_as_ushort(__float2half_rn(v[c + 0] * inv));
        o.y = __half_as_ushort(__float2half_rn(v[c + 1] * inv));
        o.z = __half_as_ushort(__float2half_rn(v[c + 2] * inv));
        o.w = __half_as_ushort(__float2half_rn(v[c + 3] * inv));
        *reinterpret_cast<ushort4*>(Ph + row * (long)S_ + tid * 8 + c) = o;
    }
}

// ---------------- launch ----------------
extern "C" void kernel_launch(void* const* d_in, const int* in_sizes, int n_in,
                              void* d_out, int out_size)
{
    const float* x  = (const float*)d_in[0];
    const float* wq = (const float*)d_in[1];
    const float* bq = (const float*)d_in[2];
    const float* wk = (const float*)d_in[3];
    const float* bk = (const float*)d_in[4];
    const float* wv = (const float*)d_in[5];
    const float* bv = (const float*)d_in[6];
    float* out = (float*)d_out;

    __half *xh, *wh, *wl, *Qh, *Kh, *Kl, *Vh, *Vl, *Ph;
    float* P;
    cudaGetSymbolAddress((void**)&xh, g_xh);
    cudaGetSymbolAddress((void**)&wh, g_wh); cudaGetSymbolAddress((void**)&wl, g_wl);
    cudaGetSymbolAddress((void**)&Qh, g_Qh);
    cudaGetSymbolAddress((void**)&Kh, g_Kh); cudaGetSymbolAddress((void**)&Kl, g_Kl);
    cudaGetSymbolAddress((void**)&Vh, g_Vh); cudaGetSymbolAddress((void**)&Vl, g_Vl);
    cudaGetSymbolAddress((void**)&P,  g_P);
    cudaGetSymbolAddress((void**)&Ph, g_Ph);

    cudaFuncSetAttribute(gemm_asym, cudaFuncAttributeMaxDynamicSharedMemorySize, SMEM_SZ);

    const long nx = (long)MQ * E_;
    const long nw = (long)E_ * E_;
    conv_f16 <<<(unsigned)(nx / 4 / 256), 256>>>(x, xh, nx);
    split_f16<<<(unsigned)(nw / 4 / 256), 256>>>(wq, wh + 0 * nw, wl + 0 * nw, nw);
    split_f16<<<(unsigned)(nw / 4 / 256), 256>>>(wk, wh + 1 * nw, wl + 1 * nw, nw);
    split_f16<<<(unsigned)(nw / 4 / 256), 256>>>(wv, wh + 2 * nw, wl + 2 * nw, nw);

    // QKV projections: M=8192, N=1024, K=1024
    dim3 g1(E_ / NT, MQ / MT, 1);
    gemm_asym<<<g1, NTH, SMEM_SZ>>>(xh, wh + 0 * nw, wl + 0 * nw, bq,
                                    nullptr, Qh, nullptr, E_, E_, 1.f, 0, 0, 0, 0);
    gemm_asym<<<g1, NTH, SMEM_SZ>>>(xh, wh + 1 * nw, wl + 1 * nw, bk,
                                    nullptr, Kh, Kl, E_, E_, 1.f, 0, 0, 0, 1);
    gemm_asym<<<g1, NTH, SMEM_SZ>>>(xh, wh + 2 * nw, wl + 2 * nw, bv,
                                    nullptr, Vh, Vl, E_, E_, 1.f, 0, 0, 0, 2);

    // scores = Q (Kh+Kl)^T / 32 : per-batch M=N=2048, K=1024
    dim3 g2(S_ / NT, S_ / MT, B_);
    gemm_asym<<<g2, NTH, SMEM_SZ>>>(Qh, Kh, Kl, nullptr,
                                    P, nullptr, nullptr, S_, E_, 0.03125f,
                                    (long)S_ * E_, (long)S_ * E_, (long)S_ * S_, 3);

    softmax_f16<<<B_ * S_, 256>>>(P, Ph);

    // out = P (Vh+Vl) : per-batch M=2048, N=1024, K=2048 (B = V^T, NT form)
    dim3 g3(E_ / NT, S_ / MT, B_);
    gemm_asym<<<g3, NTH, SMEM_SZ>>>(Ph, Vh, Vl, nullptr,
                                    out, nullptr, nullptr, E_, S_, 1.f,
                                    (long)S_ * S_, (long)E_ * S_, (long)S_ * E_, 3);
}

// round 7
// speedup vs baseline: 5.1347x; 1.2693x over previous
#include <cuda_runtime.h>
#include <cuda_fp16.h>
#include <math.h>
#include <stdint.h>

#define B_ 4
#define S_ 2048
#define E_ 1024
#define MQ (B_*S_)

// ---------------- device scratch (allocation-free) ----------------
__device__ __half g_xh[(size_t)MQ*E_];
__device__ __half g_wh[3][(size_t)E_*E_], g_wl[3][(size_t)E_*E_];
__device__ __half g_Qh[(size_t)MQ*E_];
__device__ __half g_Kh[(size_t)MQ*E_];
__device__ __half g_Vh[(size_t)MQ*E_];        // V^T: [B][E][S]
__device__ float  g_P [(size_t)B_*S_*S_];
__device__ __half g_Ph[(size_t)B_*S_*S_];

// ---------------- helpers ----------------
__device__ __forceinline__ uint32_t smem_u32(const void* p) {
    uint32_t a;
    asm("{ .reg .u64 t; cvta.to.shared.u64 t, %1; cvt.u32.u64 %0, t; }" : "=r"(a) : "l"(p));
    return a;
}
__device__ __forceinline__ void cp16(uint32_t s, const void* g) {
    asm volatile("cp.async.cg.shared.global [%0], [%1], 16;" :: "r"(s), "l"(g) : "memory");
}
#define CP_COMMIT() asm volatile("cp.async.commit_group;" ::: "memory")
#define CP_WAIT1()  asm volatile("cp.async.wait_group 1;" ::: "memory")
#define CP_WAIT0()  asm volatile("cp.async.wait_group 0;" ::: "memory")

__device__ __forceinline__ void ldsm4(uint32_t& r0, uint32_t& r1, uint32_t& r2, uint32_t& r3, uint32_t a) {
    asm volatile("ldmatrix.sync.aligned.m8n8.x4.shared.b16 {%0,%1,%2,%3}, [%4];"
                 : "=r"(r0), "=r"(r1), "=r"(r2), "=r"(r3) : "r"(a));
}
__device__ __forceinline__ void mma_f32(float* c, const uint32_t* a, const uint32_t* b) {
    asm volatile("mma.sync.aligned.m16n8k16.row.col.f32.f16.f16.f32 "
                 "{%0,%1,%2,%3}, {%4,%5,%6,%7}, {%8,%9}, {%0,%1,%2,%3};"
                 : "+f"(c[0]), "+f"(c[1]), "+f"(c[2]), "+f"(c[3])
                 : "r"(a[0]), "r"(a[1]), "r"(a[2]), "r"(a[3]), "r"(b[0]), "r"(b[1]));
}

// ---------------- fp16 GEMM, optionally split-B ----------------
// D[M,N] = alpha*(A @ (Bh[+Bl])^T) (+ bias[n]);  A plain fp16.
// modes: 0 = fp16 plain row-major (Oh)
//        2 = fp16 plain transposed [b][n][s] (V path)
//        3 = fp32 row-major (Cf)
#define MT 128
#define NT 128
#define KT 32
#define NTH 256
#define NSTG 3
#define ARR_B (128*40*2)              // 128 rows * 80 B (32 elems + 8 pad)

template<bool SB>
__global__ __launch_bounds__(NTH, 1)
void gemm_asym(const __half* __restrict__ A, const __half* __restrict__ Bh,
               const __half* __restrict__ Bl, const float* __restrict__ bias,
               float* __restrict__ Cf, __half* __restrict__ Oh,
               int Ndim, int Kdim, float alpha,
               long sA, long sB, long sC, int mode)
{
    constexpr uint32_t STG_B = (SB ? 3 : 2) * ARR_B;
    extern __shared__ char smem[];
    const uint32_t sb = smem_u32(smem);
    const int tid = threadIdx.x, lane = tid & 31, wid = tid >> 5;
    const int wm = (wid >> 2) * 64;          // warp M offset (0,64)
    const int wn = (wid & 3) * 32;           // warp N offset (0,32,64,96)
    const long z = blockIdx.z;
    A += z * sA; Bh += z * sB; if (SB) Bl += z * sB;
    const int m0 = blockIdx.y * MT, n0 = blockIdx.x * NT;
    const int kt = Kdim / KT;

    auto load_tile = [&](int it, int stage) {
        const uint32_t st = sb + stage * STG_B;
        const long k0 = (long)it * KT;
        #pragma unroll
        for (int arr = 0; arr < (SB ? 3 : 2); arr++) {
            const __half* src = (arr == 0) ? A : (arr == 1) ? Bh : Bl;
            const int rbase = (arr == 0) ? m0 : n0;
            const uint32_t ab = st + arr * ARR_B;
            #pragma unroll
            for (int i = 0; i < 2; i++) {
                int c = tid + i * NTH;
                int row = c >> 2, kc = c & 3;
                cp16(ab + row * 80 + kc * 16,
                     src + (long)(rbase + row) * Kdim + k0 + kc * 8);
            }
        }
    };

    float acc[4][4][4];
    #pragma unroll
    for (int i = 0; i < 4; i++)
        #pragma unroll
        for (int j = 0; j < 4; j++)
            #pragma unroll
            for (int q = 0; q < 4; q++) acc[i][j][q] = 0.f;

    const uint32_t a_row = (lane & 15), a_k = (lane >> 4) * 8;
    const uint32_t b_n = ((lane >> 4) & 1) * 8 + (lane & 7), b_k = ((lane >> 3) & 1) * 8;

    load_tile(0, 0); CP_COMMIT();
    load_tile(1, 1); CP_COMMIT();

    for (int it = 0; it < kt; it++) {
        CP_WAIT1();
        __syncthreads();
        if (it + 2 < kt) load_tile(it + 2, (it + 2) % NSTG);
        CP_COMMIT();

        const uint32_t st = sb + (it % NSTG) * STG_B;
        #pragma unroll
        for (int ks = 0; ks < 2; ks++) {
            uint32_t ah[4][4], bh[4][2], bl[4][2];
            #pragma unroll
            for (int i = 0; i < 4; i++) {
                uint32_t off = (wm + i * 16 + a_row) * 80 + (ks * 16 + a_k) * 2;
                ldsm4(ah[i][0], ah[i][1], ah[i][2], ah[i][3], st + off);
            }
            #pragma unroll
            for (int jj = 0; jj < 2; jj++) {
                uint32_t off = (wn + jj * 16 + b_n) * 80 + (ks * 16 + b_k) * 2;
                uint32_t r0, r1, r2, r3;
                ldsm4(r0, r1, r2, r3, st + ARR_B + off);
                bh[2 * jj][0] = r0; bh[2 * jj][1] = r1; bh[2 * jj + 1][0] = r2; bh[2 * jj + 1][1] = r3;
                if (SB) {
                    ldsm4(r0, r1, r2, r3, st + 2 * ARR_B + off);
                    bl[2 * jj][0] = r0; bl[2 * jj][1] = r1; bl[2 * jj + 1][0] = r2; bl[2 * jj + 1][1] = r3;
                }
            }
            #pragma unroll
            for (int i = 0; i < 4; i++)
                #pragma unroll
                for (int j = 0; j < 4; j++) mma_f32(acc[i][j], ah[i], bh[j]);
            if (SB) {
                #pragma unroll
                for (int i = 0; i < 4; i++)
                    #pragma unroll
                    for (int j = 0; j < 4; j++) mma_f32(acc[i][j], ah[i], bl[j]);
            }
        }
    }
    CP_WAIT0();

    // ---------------- epilogue ----------------
    const int r = lane >> 2, cq = (lane & 3) * 2;

    if (mode == 2) {
        // stage tile in smem, then coalesced transposed store [b][n][s]
        __syncthreads();
        __half* sh = reinterpret_cast<__half*>(smem);   // 128 x 136 fp16
        #pragma unroll
        for (int i = 0; i < 4; i++)
            #pragma unroll
            for (int j = 0; j < 4; j++) {
                const int cl = wn + j * 8 + cq;
                #pragma unroll
                for (int h = 0; h < 2; h++) {
                    const int row = wm + i * 16 + r + h * 8;
                    float v0 = acc[i][j][2 * h + 0] * alpha;
                    float v1 = acc[i][j][2 * h + 1] * alpha;
                    if (bias) { v0 += __ldg(bias + n0 + cl); v1 += __ldg(bias + n0 + cl + 1); }
                    sh[row * 136 + cl]     = __float2half_rn(v0);
                    sh[row * 136 + cl + 1] = __float2half_rn(v1);
                }
            }
        __syncthreads();
        const int c = tid >> 1, half_ = tid & 1;
        const long bidx = (long)(m0 >> 11);
        const int sbase = (m0 & 2047) + half_ * 64;
        const long obase = bidx * E_ * S_ + (long)(n0 + c) * S_ + sbase;
        #pragma unroll
        for (int mm = 0; mm < 64; mm += 8) {
            const int m = half_ * 64 + mm;
            unsigned short uh[8];
            #pragma unroll
            for (int t = 0; t < 8; t++)
                uh[t] = __half_as_ushort(sh[(m + t) * 136 + c]);
            *reinterpret_cast<ushort4*>(Oh + obase + mm)     = make_ushort4(uh[0], uh[1], uh[2], uh[3]);
            *reinterpret_cast<ushort4*>(Oh + obase + mm + 4) = make_ushort4(uh[4], uh[5], uh[6], uh[7]);
        }
        return;
    }

    #pragma unroll
    for (int i = 0; i < 4; i++)
        #pragma unroll
        for (int j = 0; j < 4; j++) {
            const int gn = n0 + wn + j * 8 + cq;
            float bv0 = 0.f, bv1 = 0.f;
            if (bias) { bv0 = __ldg(bias + gn); bv1 = __ldg(bias + gn + 1); }
            #pragma unroll
            for (int h = 0; h < 2; h++) {
                const long gm = m0 + wm + i * 16 + r + h * 8;
                float v0 = acc[i][j][2 * h + 0] * alpha + bv0;
                float v1 = acc[i][j][2 * h + 1] * alpha + bv1;
                if (mode == 3) {
                    *reinterpret_cast<float2*>(Cf + z * sC + gm * Ndim + gn) = make_float2(v0, v1);
                } else {
                    *reinterpret_cast<ushort2*>(Oh + gm * Ndim + gn) =
                        make_ushort2(__half_as_ushort(__float2half_rn(v0)),
                                     __half_as_ushort(__float2half_rn(v1)));
                }
            }
        }
}

// ---------------- fp32 -> fp16 plain ----------------
__global__ __launch_bounds__(256)
void conv_f16(const float* __restrict__ s, __half* __restrict__ h, long n)
{
    long i = ((long)blockIdx.x * blockDim.x + threadIdx.x) * 4;
    if (i >= n) return;
    float4 v = *reinterpret_cast<const float4*>(s + i);
    *reinterpret_cast<ushort4*>(h + i) = make_ushort4(
        __half_as_ushort(__float2half_rn(v.x)), __half_as_ushort(__float2half_rn(v.y)),
        __half_as_ushort(__float2half_rn(v.z)), __half_as_ushort(__float2half_rn(v.w)));
}

// ---------------- fp32 -> fp16 hi/lo split ----------------
__global__ __launch_bounds__(256)
void split_f16(const float* __restrict__ s, __half* __restrict__ h,
               __half* __restrict__ l, long n)
{
    long i = ((long)blockIdx.x * blockDim.x + threadIdx.x) * 4;
    if (i >= n) return;
    float4 v = *reinterpret_cast<const float4*>(s + i);
    float a[4] = {v.x, v.y, v.z, v.w};
    unsigned short hh[4], ll[4];
    #pragma unroll
    for (int k = 0; k < 4; k++) {
        __half hb = __float2half_rn(a[k]);
        __half lb = __float2half_rn(a[k] - __half2float(hb));
        hh[k] = __half_as_ushort(hb); ll[k] = __half_as_ushort(lb);
    }
    *reinterpret_cast<ushort4*>(h + i) = make_ushort4(hh[0], hh[1], hh[2], hh[3]);
    *reinterpret_cast<ushort4*>(l + i) = make_ushort4(ll[0], ll[1], ll[2], ll[3]);
}

// ---------------- softmax -> fp16 plain ----------------
__global__ __launch_bounds__(256)
void softmax_f16(const float* __restrict__ P, __half* __restrict__ Ph)
{
    const long row = blockIdx.x;
    const float* p = P + row * (long)S_;
    const int tid = threadIdx.x;

    float v[8];
    float mx = -INFINITY;
    #pragma unroll
    for (int c = 0; c < 8; c += 4) {
        float4 t = *reinterpret_cast<const float4*>(p + tid * 8 + c);
        v[c] = t.x; v[c+1] = t.y; v[c+2] = t.z; v[c+3] = t.w;
        mx = fmaxf(mx, fmaxf(fmaxf(t.x, t.y), fmaxf(t.z, t.w)));
    }
    __shared__ float red[8];
    #pragma unroll
    for (int o = 16; o > 0; o >>= 1) mx = fmaxf(mx, __shfl_xor_sync(0xffffffffu, mx, o));
    if ((tid & 31) == 0) red[tid >> 5] = mx;
    __syncthreads();
    float zm = red[0];
    #pragma unroll
    for (int i = 1; i < 8; i++) zm = fmaxf(zm, red[i]);
    __syncthreads();

    float sm = 0.f;
    #pragma unroll
    for (int i = 0; i < 8; i++) { v[i] = __expf(v[i] - zm); sm += v[i]; }
    #pragma unroll
    for (int o = 16; o > 0; o >>= 1) sm += __shfl_xor_sync(0xffffffffu, sm, o);
    if ((tid & 31) == 0) red[tid >> 5] = sm;
    __syncthreads();
    float tot = 0.f;
    #pragma unroll
    for (int i = 0; i < 8; i++) tot += red[i];
    const float inv = 1.f / tot;

    #pragma unroll
    for (int c = 0; c < 8; c += 4) {
        ushort4 o;
        o.x = __half_as_ushort(__float2half_rn(v[c + 0] * inv));
        o.y = __half_as_ushort(__float2half_rn(v[c + 1] * inv));
        o.z = __half_as_ushort(__float2half_rn(v[c + 2] * inv));
        o.w = __half_as_ushort(__float2half_rn(v[c + 3] * inv));
        *reinterpret_cast<ushort4*>(Ph + row * (long)S_ + tid * 8 + c) = o;
    }
}

// ---------------- launch ----------------
extern "C" void kernel_launch(void* const* d_in, const int* in_sizes, int n_in,
                              void* d_out, int out_size)
{
    const float* x  = (const float*)d_in[0];
    const float* wq = (const float*)d_in[1];
    const float* bq = (const float*)d_in[2];
    const float* wk = (const float*)d_in[3];
    const float* bk = (const float*)d_in[4];
    const float* wv = (const float*)d_in[5];
    const float* bv = (const float*)d_in[6];
    float* out = (float*)d_out;

    __half *xh, *wh, *wl, *Qh, *Kh, *Vh, *Ph;
    float* P;
    cudaGetSymbolAddress((void**)&xh, g_xh);
    cudaGetSymbolAddress((void**)&wh, g_wh); cudaGetSymbolAddress((void**)&wl, g_wl);
    cudaGetSymbolAddress((void**)&Qh, g_Qh);
    cudaGetSymbolAddress((void**)&Kh, g_Kh);
    cudaGetSymbolAddress((void**)&Vh, g_Vh);
    cudaGetSymbolAddress((void**)&P,  g_P);
    cudaGetSymbolAddress((void**)&Ph, g_Ph);

    const int SMEM_S = NSTG * 3 * ARR_B;   // split-B: 92160
    const int SMEM_P = NSTG * 2 * ARR_B;   // plain-B: 61440
    cudaFuncSetAttribute(gemm_asym<true>,  cudaFuncAttributeMaxDynamicSharedMemorySize, SMEM_S);
    cudaFuncSetAttribute(gemm_asym<false>, cudaFuncAttributeMaxDynamicSharedMemorySize, SMEM_P);

    const long nx = (long)MQ * E_;
    const long nw = (long)E_ * E_;
    conv_f16 <<<(unsigned)(nx / 4 / 256), 256>>>(x, xh, nx);
    split_f16<<<(unsigned)(nw / 4 / 256), 256>>>(wq, wh + 0 * nw, wl + 0 * nw, nw);
    split_f16<<<(unsigned)(nw / 4 / 256), 256>>>(wk, wh + 1 * nw, wl + 1 * nw, nw);
    split_f16<<<(unsigned)(nw / 4 / 256), 256>>>(wv, wh + 2 * nw, wl + 2 * nw, nw);

    // QKV projections: M=8192, N=1024, K=1024 (W split)
    dim3 g1(E_ / NT, MQ / MT, 1);
    gemm_asym<true><<<g1, NTH, SMEM_S>>>(xh, wh + 0 * nw, wl + 0 * nw, bq,
                                         nullptr, Qh, E_, E_, 1.f, 0, 0, 0, 0);
    gemm_asym<true><<<g1, NTH, SMEM_S>>>(xh, wh + 1 * nw, wl + 1 * nw, bk,
                                         nullptr, Kh, E_, E_, 1.f, 0, 0, 0, 0);
    gemm_asym<true><<<g1, NTH, SMEM_S>>>(xh, wh + 2 * nw, wl + 2 * nw, bv,
                                         nullptr, Vh, E_, E_, 1.f, 0, 0, 0, 2);

    // scores = Q K^T / 32 : per-batch M=N=2048, K=1024 (plain x plain)
    dim3 g2(S_ / NT, S_ / MT, B_);
    gemm_asym<false><<<g2, NTH, SMEM_P>>>(Qh, Kh, nullptr, nullptr,
                                          P, nullptr, S_, E_, 0.03125f,
                                          (long)S_ * E_, (long)S_ * E_, (long)S_ * S_, 3);

    softmax_f16<<<B_ * S_, 256>>>(P, Ph);

    // out = P V : per-batch M=2048, N=1024, K=2048 (B = V^T, plain x plain)
    dim3 g3(E_ / NT, S_ / MT, B_);
    gemm_asym<false><<<g3, NTH, SMEM_P>>>(Ph, Vh, nullptr, nullptr,
                                          out, nullptr, E_, S_, 1.f,
                                          (long)S_ * S_, (long)E_ * S_, (long)S_ * E_, 3);
}

// round 8
// speedup vs baseline: 6.3222x; 1.2313x over previous
#include <cuda_runtime.h>
#include <cuda_fp16.h>
#include <math.h>
#include <stdint.h>

#define B_ 4
#define S_ 2048
#define E_ 1024
#define MQ (B_*S_)

// ---------------- device scratch (allocation-free) ----------------
__device__ __half g_xh[(size_t)MQ*E_];
__device__ __half g_wh[3][(size_t)E_*E_];
__device__ __half g_Qh[(size_t)MQ*E_];
__device__ __half g_Kh[(size_t)MQ*E_];
__device__ __half g_Vh[(size_t)MQ*E_];        // V^T: [B][E][S]
__device__ float  g_P [(size_t)B_*S_*S_];
__device__ __half g_Ph[(size_t)B_*S_*S_];

// ---------------- helpers ----------------
__device__ __forceinline__ uint32_t smem_u32(const void* p) {
    uint32_t a;
    asm("{ .reg .u64 t; cvta.to.shared.u64 t, %1; cvt.u32.u64 %0, t; }" : "=r"(a) : "l"(p));
    return a;
}
__device__ __forceinline__ void cp16(uint32_t s, const void* g) {
    asm volatile("cp.async.cg.shared.global [%0], [%1], 16;" :: "r"(s), "l"(g) : "memory");
}
#define CP_COMMIT() asm volatile("cp.async.commit_group;" ::: "memory")
#define CP_WAIT1()  asm volatile("cp.async.wait_group 1;" ::: "memory")
#define CP_WAIT0()  asm volatile("cp.async.wait_group 0;" ::: "memory")

__device__ __forceinline__ void ldsm4(uint32_t& r0, uint32_t& r1, uint32_t& r2, uint32_t& r3, uint32_t a) {
    asm volatile("ldmatrix.sync.aligned.m8n8.x4.shared.b16 {%0,%1,%2,%3}, [%4];"
                 : "=r"(r0), "=r"(r1), "=r"(r2), "=r"(r3) : "r"(a));
}
__device__ __forceinline__ void mma_f32(float* c, const uint32_t* a, const uint32_t* b) {
    asm volatile("mma.sync.aligned.m16n8k16.row.col.f32.f16.f16.f32 "
                 "{%0,%1,%2,%3}, {%4,%5,%6,%7}, {%8,%9}, {%0,%1,%2,%3};"
                 : "+f"(c[0]), "+f"(c[1]), "+f"(c[2]), "+f"(c[3])
                 : "r"(a[0]), "r"(a[1]), "r"(a[2]), "r"(a[3]), "r"(b[0]), "r"(b[1]));
}

// ---------------- plain fp16 GEMM (NT) ----------------
// D[M,N] = alpha*(A @ B^T) (+ bias[n])
// modes: 0 = fp16 row-major (Oh)
//        2 = fp16 transposed [b][n][s] (V path)
//        3 = fp32 row-major (Cf)
#define MT 128
#define NT 128
#define KT 32
#define NTH 256
#define NSTG 3
#define ARR_B (128*40*2)              // 128 rows * 80 B (32 elems + 8 pad)
#define STG_B (2*ARR_B)               // A, B
#define SMEM_SZ (NSTG*STG_B)          // 61440 B

__global__ __launch_bounds__(NTH, 1)
void gemm_f16(const __half* __restrict__ A, const __half* __restrict__ Bm,
              const float* __restrict__ bias,
              float* __restrict__ Cf, __half* __restrict__ Oh,
              int Ndim, int Kdim, float alpha,
              long sA, long sB, long sC, int mode)
{
    extern __shared__ char smem[];
    const uint32_t sb = smem_u32(smem);
    const int tid = threadIdx.x, lane = tid & 31, wid = tid >> 5;
    const int wm = (wid >> 2) * 64;          // warp M offset (0,64)
    const int wn = (wid & 3) * 32;           // warp N offset (0,32,64,96)
    const long z = blockIdx.z;
    A += z * sA; Bm += z * sB;
    const int m0 = blockIdx.y * MT, n0 = blockIdx.x * NT;
    const int kt = Kdim / KT;

    auto load_tile = [&](int it, int stage) {
        const uint32_t st = sb + stage * STG_B;
        const long k0 = (long)it * KT;
        #pragma unroll
        for (int arr = 0; arr < 2; arr++) {
            const __half* src = (arr == 0) ? A : Bm;
            const int rbase = (arr == 0) ? m0 : n0;
            const uint32_t ab = st + arr * ARR_B;
            #pragma unroll
            for (int i = 0; i < 2; i++) {
                int c = tid + i * NTH;
                int row = c >> 2, kc = c & 3;
                cp16(ab + row * 80 + kc * 16,
                     src + (long)(rbase + row) * Kdim + k0 + kc * 8);
            }
        }
    };

    float acc[4][4][4];
    #pragma unroll
    for (int i = 0; i < 4; i++)
        #pragma unroll
        for (int j = 0; j < 4; j++)
            #pragma unroll
            for (int q = 0; q < 4; q++) acc[i][j][q] = 0.f;

    const uint32_t a_row = (lane & 15), a_k = (lane >> 4) * 8;
    const uint32_t b_n = ((lane >> 4) & 1) * 8 + (lane & 7), b_k = ((lane >> 3) & 1) * 8;

    load_tile(0, 0); CP_COMMIT();
    load_tile(1, 1); CP_COMMIT();

    for (int it = 0; it < kt; it++) {
        CP_WAIT1();
        __syncthreads();
        if (it + 2 < kt) load_tile(it + 2, (it + 2) % NSTG);
        CP_COMMIT();

        const uint32_t st = sb + (it % NSTG) * STG_B;
        #pragma unroll
        for (int ks = 0; ks < 2; ks++) {
            uint32_t ah[4][4], bh[4][2];
            #pragma unroll
            for (int i = 0; i < 4; i++) {
                uint32_t off = (wm + i * 16 + a_row) * 80 + (ks * 16 + a_k) * 2;
                ldsm4(ah[i][0], ah[i][1], ah[i][2], ah[i][3], st + off);
            }
            #pragma unroll
            for (int jj = 0; jj < 2; jj++) {
                uint32_t off = (wn + jj * 16 + b_n) * 80 + (ks * 16 + b_k) * 2;
                uint32_t r0, r1, r2, r3;
                ldsm4(r0, r1, r2, r3, st + ARR_B + off);
                bh[2 * jj][0] = r0; bh[2 * jj][1] = r1; bh[2 * jj + 1][0] = r2; bh[2 * jj + 1][1] = r3;
            }
            #pragma unroll
            for (int i = 0; i < 4; i++)
                #pragma unroll
                for (int j = 0; j < 4; j++) mma_f32(acc[i][j], ah[i], bh[j]);
        }
    }
    CP_WAIT0();

    // ---------------- epilogue ----------------
    const int r = lane >> 2, cq = (lane & 3) * 2;

    if (mode == 2) {
        // stage tile in smem, then coalesced transposed store [b][n][s]
        __syncthreads();
        __half* sh = reinterpret_cast<__half*>(smem);   // 128 x 136 fp16
        #pragma unroll
        for (int i = 0; i < 4; i++)
            #pragma unroll
            for (int j = 0; j < 4; j++) {
                const int cl = wn + j * 8 + cq;
                #pragma unroll
                for (int h = 0; h < 2; h++) {
                    const int row = wm + i * 16 + r + h * 8;
                    float v0 = acc[i][j][2 * h + 0] * alpha;
                    float v1 = acc[i][j][2 * h + 1] * alpha;
                    if (bias) { v0 += __ldg(bias + n0 + cl); v1 += __ldg(bias + n0 + cl + 1); }
                    sh[row * 136 + cl]     = __float2half_rn(v0);
                    sh[row * 136 + cl + 1] = __float2half_rn(v1);
                }
            }
        __syncthreads();
        const int c = tid >> 1, half_ = tid & 1;
        const long bidx = (long)(m0 >> 11);
        const int sbase = (m0 & 2047) + half_ * 64;
        const long obase = bidx * E_ * S_ + (long)(n0 + c) * S_ + sbase;
        #pragma unroll
        for (int mm = 0; mm < 64; mm += 8) {
            const int m = half_ * 64 + mm;
            unsigned short uh[8];
            #pragma unroll
            for (int t = 0; t < 8; t++)
                uh[t] = __half_as_ushort(sh[(m + t) * 136 + c]);
            *reinterpret_cast<ushort4*>(Oh + obase + mm)     = make_ushort4(uh[0], uh[1], uh[2], uh[3]);
            *reinterpret_cast<ushort4*>(Oh + obase + mm + 4) = make_ushort4(uh[4], uh[5], uh[6], uh[7]);
        }
        return;
    }

    #pragma unroll
    for (int i = 0; i < 4; i++)
        #pragma unroll
        for (int j = 0; j < 4; j++) {
            const int gn = n0 + wn + j * 8 + cq;
            float bv0 = 0.f, bv1 = 0.f;
            if (bias) { bv0 = __ldg(bias + gn); bv1 = __ldg(bias + gn + 1); }
            #pragma unroll
            for (int h = 0; h < 2; h++) {
                const long gm = m0 + wm + i * 16 + r + h * 8;
                float v0 = acc[i][j][2 * h + 0] * alpha + bv0;
                float v1 = acc[i][j][2 * h + 1] * alpha + bv1;
                if (mode == 3) {
                    *reinterpret_cast<float2*>(Cf + z * sC + gm * Ndim + gn) = make_float2(v0, v1);
                } else {
                    *reinterpret_cast<ushort2*>(Oh + gm * Ndim + gn) =
                        make_ushort2(__half_as_ushort(__float2half_rn(v0)),
                                     __half_as_ushort(__float2half_rn(v1)));
                }
            }
        }
}

// ---------------- fp32 -> fp16 ----------------
__global__ __launch_bounds__(256)
void conv_f16(const float* __restrict__ s, __half* __restrict__ h, long n)
{
    long i = ((long)blockIdx.x * blockDim.x + threadIdx.x) * 4;
    if (i >= n) return;
    float4 v = *reinterpret_cast<const float4*>(s + i);
    *reinterpret_cast<ushort4*>(h + i) = make_ushort4(
        __half_as_ushort(__float2half_rn(v.x)), __half_as_ushort(__float2half_rn(v.y)),
        __half_as_ushort(__float2half_rn(v.z)), __half_as_ushort(__float2half_rn(v.w)));
}

// ---------------- softmax -> fp16 ----------------
__global__ __launch_bounds__(256)
void softmax_f16(const float* __restrict__ P, __half* __restrict__ Ph)
{
    const long row = blockIdx.x;
    const float* p = P + row * (long)S_;
    const int tid = threadIdx.x;

    float v[8];
    float mx = -INFINITY;
    #pragma unroll
    for (int c = 0; c < 8; c += 4) {
        float4 t = *reinterpret_cast<const float4*>(p + tid * 8 + c);
        v[c] = t.x; v[c+1] = t.y; v[c+2] = t.z; v[c+3] = t.w;
        mx = fmaxf(mx, fmaxf(fmaxf(t.x, t.y), fmaxf(t.z, t.w)));
    }
    __shared__ float red[8];
    #pragma unroll
    for (int o = 16; o > 0; o >>= 1) mx = fmaxf(mx, __shfl_xor_sync(0xffffffffu, mx, o));
    if ((tid & 31) == 0) red[tid >> 5] = mx;
    __syncthreads();
    float zm = red[0];
    #pragma unroll
    for (int i = 1; i < 8; i++) zm = fmaxf(zm, red[i]);
    __syncthreads();

    float sm = 0.f;
    #pragma unroll
    for (int i = 0; i < 8; i++) { v[i] = __expf(v[i] - zm); sm += v[i]; }
    #pragma unroll
    for (int o = 16; o > 0; o >>= 1) sm += __shfl_xor_sync(0xffffffffu, sm, o);
    if ((tid & 31) == 0) red[tid >> 5] = sm;
    __syncthreads();
    float tot = 0.f;
    #pragma unroll
    for (int i = 0; i < 8; i++) tot += red[i];
    const float inv = 1.f / tot;

    #pragma unroll
    for (int c = 0; c < 8; c += 4) {
        ushort4 o;
        o.x = __half_as_ushort(__float2half_rn(v[c + 0] * inv));
        o.y = __half_as_ushort(__float2half_rn(v[c + 1] * inv));
        o.z = __half_as_ushort(__float2half_rn(v[c + 2] * inv));
        o.w = __half_as_ushort(__float2half_rn(v[c + 3] * inv));
        *reinterpret_cast<ushort4*>(Ph + row * (long)S_ + tid * 8 + c) = o;
    }
}

// ---------------- launch ----------------
extern "C" void kernel_launch(void* const* d_in, const int* in_sizes, int n_in,
                              void* d_out, int out_size)
{
    const float* x  = (const float*)d_in[0];
    const float* wq = (const float*)d_in[1];
    const float* bq = (const float*)d_in[2];
    const float* wk = (const float*)d_in[3];
    const float* bk = (const float*)d_in[4];
    const float* wv = (const float*)d_in[5];
    const float* bv = (const float*)d_in[6];
    float* out = (float*)d_out;

    __half *xh, *wh, *Qh, *Kh, *Vh, *Ph;
    float* P;
    cudaGetSymbolAddress((void**)&xh, g_xh);
    cudaGetSymbolAddress((void**)&wh, g_wh);
    cudaGetSymbolAddress((void**)&Qh, g_Qh);
    cudaGetSymbolAddress((void**)&Kh, g_Kh);
    cudaGetSymbolAddress((void**)&Vh, g_Vh);
    cudaGetSymbolAddress((void**)&P,  g_P);
    cudaGetSymbolAddress((void**)&Ph, g_Ph);

    cudaFuncSetAttribute(gemm_f16, cudaFuncAttributeMaxDynamicSharedMemorySize, SMEM_SZ);

    const long nx = (long)MQ * E_;
    const long nw = (long)E_ * E_;
    conv_f16<<<(unsigned)(nx / 4 / 256), 256>>>(x, xh, nx);
    conv_f16<<<(unsigned)(nw / 4 / 256), 256>>>(wq, wh + 0 * nw, nw);
    conv_f16<<<(unsigned)(nw / 4 / 256), 256>>>(wk, wh + 1 * nw, nw);
    conv_f16<<<(unsigned)(nw / 4 / 256), 256>>>(wv, wh + 2 * nw, nw);

    // QKV projections: M=8192, N=1024, K=1024
    dim3 g1(E_ / NT, MQ / MT, 1);
    gemm_f16<<<g1, NTH, SMEM_SZ>>>(xh, wh + 0 * nw, bq, nullptr, Qh,
                                   E_, E_, 1.f, 0, 0, 0, 0);
    gemm_f16<<<g1, NTH, SMEM_SZ>>>(xh, wh + 1 * nw, bk, nullptr, Kh,
                                   E_, E_, 1.f, 0, 0, 0, 0);
    gemm_f16<<<g1, NTH, SMEM_SZ>>>(xh, wh + 2 * nw, bv, nullptr, Vh,
                                   E_, E_, 1.f, 0, 0, 0, 2);

    // scores = Q K^T / 32 : per-batch M=N=2048, K=1024
    dim3 g2(S_ / NT, S_ / MT, B_);
    gemm_f16<<<g2, NTH, SMEM_SZ>>>(Qh, Kh, nullptr, P, nullptr,
                                   S_, E_, 0.03125f,
                                   (long)S_ * E_, (long)S_ * E_, (long)S_ * S_, 3);

    softmax_f16<<<B_ * S_, 256>>>(P, Ph);

    // out = P V : per-batch M=2048, N=1024, K=2048 (B = V^T)
    dim3 g3(E_ / NT, S_ / MT, B_);
    gemm_f16<<<g3, NTH, SMEM_SZ>>>(Ph, Vh, nullptr, out, nullptr,
                                   E_, S_, 1.f,
                                   (long)S_ * S_, (long)E_ * S_, (long)S_ * E_, 3);
}

// round 9
// speedup vs baseline: 8.3856x; 1.3264x over previous
#include <cuda_runtime.h>
#include <cuda_fp16.h>
#include <math.h>
#include <stdint.h>

#define B_ 4
#define S_ 2048
#define E_ 1024
#define MQ (B_*S_)

// ---------------- device scratch (allocation-free) ----------------
__device__ __half g_xh[(size_t)MQ*E_];
__device__ __half g_wh[3][(size_t)E_*E_];
__device__ __half g_Qh[(size_t)MQ*E_];
__device__ __half g_Kh[(size_t)MQ*E_];
__device__ __half g_Vh[(size_t)MQ*E_];        // V^T: [B][E][S]
__device__ float  g_P [(size_t)B_*S_*S_];
__device__ __half g_Ph[(size_t)B_*S_*S_];

// ---------------- helpers ----------------
__device__ __forceinline__ uint32_t smem_u32(const void* p) {
    uint32_t a;
    asm("{ .reg .u64 t; cvta.to.shared.u64 t, %1; cvt.u32.u64 %0, t; }" : "=r"(a) : "l"(p));
    return a;
}
__device__ __forceinline__ void cp16(uint32_t s, const void* g) {
    asm volatile("cp.async.cg.shared.global [%0], [%1], 16;" :: "r"(s), "l"(g) : "memory");
}
#define CP_COMMIT() asm volatile("cp.async.commit_group;" ::: "memory")
#define CP_WAIT1()  asm volatile("cp.async.wait_group 1;" ::: "memory")
#define CP_WAIT0()  asm volatile("cp.async.wait_group 0;" ::: "memory")

__device__ __forceinline__ void ldsm4(uint32_t& r0, uint32_t& r1, uint32_t& r2, uint32_t& r3, uint32_t a) {
    asm volatile("ldmatrix.sync.aligned.m8n8.x4.shared.b16 {%0,%1,%2,%3}, [%4];"
                 : "=r"(r0), "=r"(r1), "=r"(r2), "=r"(r3) : "r"(a));
}
__device__ __forceinline__ void mma_f32(float* c, const uint32_t* a, const uint32_t* b) {
    asm volatile("mma.sync.aligned.m16n8k16.row.col.f32.f16.f16.f32 "
                 "{%0,%1,%2,%3}, {%4,%5,%6,%7}, {%8,%9}, {%0,%1,%2,%3};"
                 : "+f"(c[0]), "+f"(c[1]), "+f"(c[2]), "+f"(c[3])
                 : "r"(a[0]), "r"(a[1]), "r"(a[2]), "r"(a[3]), "r"(b[0]), "r"(b[1]));
}

// ---------------- plain fp16 GEMM (NT) ----------------
// D[M,N] = alpha*(A @ B^T) (+ bias[n])
// modes: 0 = fp16 row-major (Oh)
//        2 = fp16 transposed [b][n][s] (V path)
//        3 = fp32 row-major (Cf)
//        4 = QKV-fused: z selects bias/out (bias,b2,b3 / Oh,O2,O3), z==2 -> mode 2
#define MT 128
#define NT 128
#define KT 32
#define NTH 256
#define NSTG 3
#define ARR_B (128*40*2)              // 128 rows * 80 B (32 elems + 8 pad)
#define STG_B (2*ARR_B)               // A, B
#define SMEM_SZ (NSTG*STG_B)          // 61440 B

__global__ __launch_bounds__(NTH, 2)
void gemm_f16(const __half* __restrict__ A, const __half* __restrict__ Bm,
              const float* __restrict__ bias, const float* __restrict__ bias2,
              const float* __restrict__ bias3,
              float* __restrict__ Cf, __half* __restrict__ Oh,
              __half* __restrict__ O2, __half* __restrict__ O3,
              int Ndim, int Kdim, float alpha,
              long sA, long sB, long sC, int mode_in)
{
    extern __shared__ char smem[];
    const uint32_t sb = smem_u32(smem);
    const int tid = threadIdx.x, lane = tid & 31, wid = tid >> 5;
    const int wm = (wid >> 2) * 64;          // warp M offset (0,64)
    const int wn = (wid & 3) * 32;           // warp N offset (0,32,64,96)
    const long z = blockIdx.z;
    A += z * sA; Bm += z * sB;
    int mode = mode_in;
    if (mode == 4) {
        if (z == 1) { bias = bias2; Oh = O2; }
        else if (z == 2) { bias = bias3; Oh = O3; }
        mode = (z == 2) ? 2 : 0;
    }
    const int m0 = blockIdx.y * MT, n0 = blockIdx.x * NT;
    const int kt = Kdim / KT;

    auto load_tile = [&](int it, int stage) {
        const uint32_t st = sb + stage * STG_B;
        const long k0 = (long)it * KT;
        #pragma unroll
        for (int arr = 0; arr < 2; arr++) {
            const __half* src = (arr == 0) ? A : Bm;
            const int rbase = (arr == 0) ? m0 : n0;
            const uint32_t ab = st + arr * ARR_B;
            #pragma unroll
            for (int i = 0; i < 2; i++) {
                int c = tid + i * NTH;
                int row = c >> 2, kc = c & 3;
                cp16(ab + row * 80 + kc * 16,
                     src + (long)(rbase + row) * Kdim + k0 + kc * 8);
            }
        }
    };

    float acc[4][4][4];
    #pragma unroll
    for (int i = 0; i < 4; i++)
        #pragma unroll
        for (int j = 0; j < 4; j++)
            #pragma unroll
            for (int q = 0; q < 4; q++) acc[i][j][q] = 0.f;

    const uint32_t a_row = (lane & 15), a_k = (lane >> 4) * 8;
    const uint32_t b_n = ((lane >> 4) & 1) * 8 + (lane & 7), b_k = ((lane >> 3) & 1) * 8;

    load_tile(0, 0); CP_COMMIT();
    load_tile(1, 1); CP_COMMIT();

    for (int it = 0; it < kt; it++) {
        CP_WAIT1();
        __syncthreads();
        if (it + 2 < kt) load_tile(it + 2, (it + 2) % NSTG);
        CP_COMMIT();

        const uint32_t st = sb + (it % NSTG) * STG_B;
        #pragma unroll
        for (int ks = 0; ks < 2; ks++) {
            uint32_t ah[4][4], bh[4][2];
            #pragma unroll
            for (int i = 0; i < 4; i++) {
                uint32_t off = (wm + i * 16 + a_row) * 80 + (ks * 16 + a_k) * 2;
                ldsm4(ah[i][0], ah[i][1], ah[i][2], ah[i][3], st + off);
            }
            #pragma unroll
            for (int jj = 0; jj < 2; jj++) {
                uint32_t off = (wn + jj * 16 + b_n) * 80 + (ks * 16 + b_k) * 2;
                uint32_t r0, r1, r2, r3;
                ldsm4(r0, r1, r2, r3, st + ARR_B + off);
                bh[2 * jj][0] = r0; bh[2 * jj][1] = r1; bh[2 * jj + 1][0] = r2; bh[2 * jj + 1][1] = r3;
            }
            #pragma unroll
            for (int i = 0; i < 4; i++)
                #pragma unroll
                for (int j = 0; j < 4; j++) mma_f32(acc[i][j], ah[i], bh[j]);
        }
    }
    CP_WAIT0();

    // ---------------- epilogue ----------------
    const int r = lane >> 2, cq = (lane & 3) * 2;

    if (mode == 2) {
        // stage tile in smem, then coalesced transposed store [b][n][s]
        __syncthreads();
        __half* sh = reinterpret_cast<__half*>(smem);   // 128 x 136 fp16
        #pragma unroll
        for (int i = 0; i < 4; i++)
            #pragma unroll
            for (int j = 0; j < 4; j++) {
                const int cl = wn + j * 8 + cq;
                #pragma unroll
                for (int h = 0; h < 2; h++) {
                    const int row = wm + i * 16 + r + h * 8;
                    float v0 = acc[i][j][2 * h + 0] * alpha;
                    float v1 = acc[i][j][2 * h + 1] * alpha;
                    if (bias) { v0 += __ldg(bias + n0 + cl); v1 += __ldg(bias + n0 + cl + 1); }
                    sh[row * 136 + cl]     = __float2half_rn(v0);
                    sh[row * 136 + cl + 1] = __float2half_rn(v1);
                }
            }
        __syncthreads();
        const int c = tid >> 1, half_ = tid & 1;
        const long bidx = (long)(m0 >> 11);
        const int sbase = (m0 & 2047) + half_ * 64;
        const long obase = bidx * E_ * S_ + (long)(n0 + c) * S_ + sbase;
        #pragma unroll
        for (int mm = 0; mm < 64; mm += 8) {
            const int m = half_ * 64 + mm;
            unsigned short uh[8];
            #pragma unroll
            for (int t = 0; t < 8; t++)
                uh[t] = __half_as_ushort(sh[(m + t) * 136 + c]);
            *reinterpret_cast<ushort4*>(Oh + obase + mm)     = make_ushort4(uh[0], uh[1], uh[2], uh[3]);
            *reinterpret_cast<ushort4*>(Oh + obase + mm + 4) = make_ushort4(uh[4], uh[5], uh[6], uh[7]);
        }
        return;
    }

    #pragma unroll
    for (int i = 0; i < 4; i++)
        #pragma unroll
        for (int j = 0; j < 4; j++) {
            const int gn = n0 + wn + j * 8 + cq;
            float bv0 = 0.f, bv1 = 0.f;
            if (bias) { bv0 = __ldg(bias + gn); bv1 = __ldg(bias + gn + 1); }
            #pragma unroll
            for (int h = 0; h < 2; h++) {
                const long gm = m0 + wm + i * 16 + r + h * 8;
                float v0 = acc[i][j][2 * h + 0] * alpha + bv0;
                float v1 = acc[i][j][2 * h + 1] * alpha + bv1;
                if (mode == 3) {
                    *reinterpret_cast<float2*>(Cf + z * sC + gm * Ndim + gn) = make_float2(v0, v1);
                } else {
                    *reinterpret_cast<ushort2*>(Oh + gm * Ndim + gn) =
                        make_ushort2(__half_as_ushort(__float2half_rn(v0)),
                                     __half_as_ushort(__float2half_rn(v1)));
                }
            }
        }
}

// ---------------- fp32 -> fp16 ----------------
__global__ __launch_bounds__(256)
void conv_f16(const float* __restrict__ s, __half* __restrict__ h, long n)
{
    long i = ((long)blockIdx.x * blockDim.x + threadIdx.x) * 4;
    if (i >= n) return;
    float4 v = *reinterpret_cast<const float4*>(s + i);
    *reinterpret_cast<ushort4*>(h + i) = make_ushort4(
        __half_as_ushort(__float2half_rn(v.x)), __half_as_ushort(__float2half_rn(v.y)),
        __half_as_ushort(__float2half_rn(v.z)), __half_as_ushort(__float2half_rn(v.w)));
}

// ---------------- softmax -> fp16 ----------------
__global__ __launch_bounds__(256)
void softmax_f16(const float* __restrict__ P, __half* __restrict__ Ph)
{
    const long row = blockIdx.x;
    const float* p = P + row * (long)S_;
    const int tid = threadIdx.x;

    float v[8];
    float mx = -INFINITY;
    #pragma unroll
    for (int c = 0; c < 8; c += 4) {
        float4 t = *reinterpret_cast<const float4*>(p + tid * 8 + c);
        v[c] = t.x; v[c+1] = t.y; v[c+2] = t.z; v[c+3] = t.w;
        mx = fmaxf(mx, fmaxf(fmaxf(t.x, t.y), fmaxf(t.z, t.w)));
    }
    __shared__ float red[8];
    #pragma unroll
    for (int o = 16; o > 0; o >>= 1) mx = fmaxf(mx, __shfl_xor_sync(0xffffffffu, mx, o));
    if ((tid & 31) == 0) red[tid >> 5] = mx;
    __syncthreads();
    float zm = red[0];
    #pragma unroll
    for (int i = 1; i < 8; i++) zm = fmaxf(zm, red[i]);
    __syncthreads();

    float sm = 0.f;
    #pragma unroll
    for (int i = 0; i < 8; i++) { v[i] = __expf(v[i] - zm); sm += v[i]; }
    #pragma unroll
    for (int o = 16; o > 0; o >>= 1) sm += __shfl_xor_sync(0xffffffffu, sm, o);
    if ((tid & 31) == 0) red[tid >> 5] = sm;
    __syncthreads();
    float tot = 0.f;
    #pragma unroll
    for (int i = 0; i < 8; i++) tot += red[i];
    const float inv = 1.f / tot;

    #pragma unroll
    for (int c = 0; c < 8; c += 4) {
        ushort4 o;
        o.x = __half_as_ushort(__float2half_rn(v[c + 0] * inv));
        o.y = __half_as_ushort(__float2half_rn(v[c + 1] * inv));
        o.z = __half_as_ushort(__float2half_rn(v[c + 2] * inv));
        o.w = __half_as_ushort(__float2half_rn(v[c + 3] * inv));
        *reinterpret_cast<ushort4*>(Ph + row * (long)S_ + tid * 8 + c) = o;
    }
}

// ---------------- launch ----------------
extern "C" void kernel_launch(void* const* d_in, const int* in_sizes, int n_in,
                              void* d_out, int out_size)
{
    const float* x  = (const float*)d_in[0];
    const float* wq = (const float*)d_in[1];
    const float* bq = (const float*)d_in[2];
    const float* wk = (const float*)d_in[3];
    const float* bk = (const float*)d_in[4];
    const float* wv = (const float*)d_in[5];
    const float* bv = (const float*)d_in[6];
    float* out = (float*)d_out;

    __half *xh, *wh, *Qh, *Kh, *Vh, *Ph;
    float* P;
    cudaGetSymbolAddress((void**)&xh, g_xh);
    cudaGetSymbolAddress((void**)&wh, g_wh);
    cudaGetSymbolAddress((void**)&Qh, g_Qh);
    cudaGetSymbolAddress((void**)&Kh, g_Kh);
    cudaGetSymbolAddress((void**)&Vh, g_Vh);
    cudaGetSymbolAddress((void**)&P,  g_P);
    cudaGetSymbolAddress((void**)&Ph, g_Ph);

    cudaFuncSetAttribute(gemm_f16, cudaFuncAttributeMaxDynamicSharedMemorySize, SMEM_SZ);

    const long nx = (long)MQ * E_;
    const long nw = (long)E_ * E_;
    conv_f16<<<(unsigned)(nx / 4 / 256), 256>>>(x, xh, nx);
    conv_f16<<<(unsigned)(nw / 4 / 256), 256>>>(wq, wh + 0 * nw, nw);
    conv_f16<<<(unsigned)(nw / 4 / 256), 256>>>(wk, wh + 1 * nw, nw);
    conv_f16<<<(unsigned)(nw / 4 / 256), 256>>>(wv, wh + 2 * nw, nw);

    // QKV projections fused: grid.z selects W slice / bias / output; M=8192, N=1024, K=1024
    dim3 g1(E_ / NT, MQ / MT, 3);
    gemm_f16<<<g1, NTH, SMEM_SZ>>>(xh, wh, bq, bk, bv,
                                   nullptr, Qh, Kh, Vh,
                                   E_, E_, 1.f, 0, nw, 0, 4);

    // scores = Q K^T / 32 : per-batch M=N=2048, K=1024
    dim3 g2(S_ / NT, S_ / MT, B_);
    gemm_f16<<<g2, NTH, SMEM_SZ>>>(Qh, Kh, nullptr, nullptr, nullptr,
                                   P, nullptr, nullptr, nullptr,
                                   S_, E_, 0.03125f,
                                   (long)S_ * E_, (long)S_ * E_, (long)S_ * S_, 3);

    softmax_f16<<<B_ * S_, 256>>>(P, Ph);

    // out = P V : per-batch M=2048, N=1024, K=2048 (B = V^T)
    dim3 g3(E_ / NT, S_ / MT, B_);
    gemm_f16<<<g3, NTH, SMEM_SZ>>>(Ph, Vh, nullptr, nullptr, nullptr,
                                   out, nullptr, nullptr, nullptr,
                                   E_, S_, 1.f,
                                   (long)S_ * S_, (long)E_ * S_, (long)S_ * E_, 3);
}

// round 10
// speedup vs baseline: 9.0229x; 1.0760x over previous
#include <cuda_runtime.h>
#include <cuda_fp16.h>
#include <math.h>
#include <stdint.h>

#define B_ 4
#define S_ 2048
#define E_ 1024
#define MQ (B_*S_)

// ---------------- device scratch (allocation-free) ----------------
__device__ __half g_xh[(size_t)MQ*E_];
__device__ __half g_wh[3][(size_t)E_*E_];
__device__ __half g_Qh[(size_t)MQ*E_];
__device__ __half g_Kh[(size_t)MQ*E_];
__device__ __half g_Vh[(size_t)MQ*E_];        // V^T: [B][E][S]
__device__ float  g_P [(size_t)B_*S_*S_];
__device__ __half g_Ph[(size_t)B_*S_*S_];

// ---------------- helpers ----------------
__device__ __forceinline__ uint32_t smem_u32(const void* p) {
    uint32_t a;
    asm("{ .reg .u64 t; cvta.to.shared.u64 t, %1; cvt.u32.u64 %0, t; }" : "=r"(a) : "l"(p));
    return a;
}
__device__ __forceinline__ void cp16(uint32_t s, const void* g) {
    asm volatile("cp.async.cg.shared.global [%0], [%1], 16;" :: "r"(s), "l"(g) : "memory");
}
#define CP_COMMIT() asm volatile("cp.async.commit_group;" ::: "memory")
#define CP_WAIT1()  asm volatile("cp.async.wait_group 1;" ::: "memory")
#define CP_WAIT0()  asm volatile("cp.async.wait_group 0;" ::: "memory")

__device__ __forceinline__ void ldsm4(uint32_t& r0, uint32_t& r1, uint32_t& r2, uint32_t& r3, uint32_t a) {
    asm volatile("ldmatrix.sync.aligned.m8n8.x4.shared.b16 {%0,%1,%2,%3}, [%4];"
                 : "=r"(r0), "=r"(r1), "=r"(r2), "=r"(r3) : "r"(a));
}
__device__ __forceinline__ void mma_f32(float* c, const uint32_t* a, const uint32_t* b) {
    asm volatile("mma.sync.aligned.m16n8k16.row.col.f32.f16.f16.f32 "
                 "{%0,%1,%2,%3}, {%4,%5,%6,%7}, {%8,%9}, {%0,%1,%2,%3};"
                 : "+f"(c[0]), "+f"(c[1]), "+f"(c[2]), "+f"(c[3])
                 : "r"(a[0]), "r"(a[1]), "r"(a[2]), "r"(a[3]), "r"(b[0]), "r"(b[1]));
}

// ---------------- plain fp16 GEMM (NT), KT=64 ----------------
// D[M,N] = alpha*(A @ B^T) (+ bias[n])
// modes: 0 = fp16 row-major (Oh)
//        2 = fp16 transposed [b][n][s] (V path)
//        3 = fp32 row-major (Cf)
//        4 = QKV-fused: z selects bias/out (bias,b2,b3 / Oh,O2,O3), z==2 -> mode 2
#define MT 128
#define NT 128
#define KT 64
#define NTH 256
#define NSTG 3
#define PITCH 144                     // (64 + 8 pad) halves per row -> 144 B
#define ARR_B (128*PITCH)             // 18432 B per operand tile
#define STG_B (2*ARR_B)               // A, B = 36864 B
#define SMEM_SZ (NSTG*STG_B)          // 110592 B

__global__ __launch_bounds__(NTH, 2)
void gemm_f16(const __half* __restrict__ A, const __half* __restrict__ Bm,
              const float* __restrict__ bias, const float* __restrict__ bias2,
              const float* __restrict__ bias3,
              float* __restrict__ Cf, __half* __restrict__ Oh,
              __half* __restrict__ O2, __half* __restrict__ O3,
              int Ndim, int Kdim, float alpha,
              long sA, long sB, long sC, int mode_in)
{
    extern __shared__ char smem[];
    const uint32_t sb = smem_u32(smem);
    const int tid = threadIdx.x, lane = tid & 31, wid = tid >> 5;
    const int wm = (wid >> 2) * 64;          // warp M offset (0,64)
    const int wn = (wid & 3) * 32;           // warp N offset (0,32,64,96)
    const long z = blockIdx.z;
    A += z * sA; Bm += z * sB;
    int mode = mode_in;
    if (mode == 4) {
        if (z == 1) { bias = bias2; Oh = O2; }
        else if (z == 2) { bias = bias3; Oh = O3; }
        mode = (z == 2) ? 2 : 0;
    }
    const int m0 = blockIdx.y * MT, n0 = blockIdx.x * NT;
    const int kt = Kdim / KT;

    // loader: 2 arrays x 1024 16B-chunks; 8 chunks/thread
    auto load_tile = [&](int it, int stage) {
        const uint32_t st = sb + stage * STG_B;
        const long k0 = (long)it * KT;
        #pragma unroll
        for (int arr = 0; arr < 2; arr++) {
            const __half* src = (arr == 0) ? A : Bm;
            const int rbase = (arr == 0) ? m0 : n0;
            const uint32_t ab = st + arr * ARR_B;
            #pragma unroll
            for (int i = 0; i < 4; i++) {
                int c = tid + i * NTH;
                int row = c >> 3, kc = c & 7;
                cp16(ab + row * PITCH + kc * 16,
                     src + (long)(rbase + row) * Kdim + k0 + kc * 8);
            }
        }
    };

    float acc[4][4][4];
    #pragma unroll
    for (int i = 0; i < 4; i++)
        #pragma unroll
        for (int j = 0; j < 4; j++)
            #pragma unroll
            for (int q = 0; q < 4; q++) acc[i][j][q] = 0.f;

    const uint32_t a_row = (lane & 15), a_k = (lane >> 4) * 8;
    const uint32_t b_n = ((lane >> 4) & 1) * 8 + (lane & 7), b_k = ((lane >> 3) & 1) * 8;

    load_tile(0, 0); CP_COMMIT();
    load_tile(1, 1); CP_COMMIT();

    for (int it = 0; it < kt; it++) {
        CP_WAIT1();
        __syncthreads();
        if (it + 2 < kt) load_tile(it + 2, (it + 2) % NSTG);
        CP_COMMIT();

        const uint32_t st = sb + (it % NSTG) * STG_B;
        #pragma unroll
        for (int ks = 0; ks < 4; ks++) {
            uint32_t ah[4][4], bh[4][2];
            #pragma unroll
            for (int i = 0; i < 4; i++) {
                uint32_t off = (wm + i * 16 + a_row) * PITCH + (ks * 16 + a_k) * 2;
                ldsm4(ah[i][0], ah[i][1], ah[i][2], ah[i][3], st + off);
            }
            #pragma unroll
            for (int jj = 0; jj < 2; jj++) {
                uint32_t off = (wn + jj * 16 + b_n) * PITCH + (ks * 16 + b_k) * 2;
                uint32_t r0, r1, r2, r3;
                ldsm4(r0, r1, r2, r3, st + ARR_B + off);
                bh[2 * jj][0] = r0; bh[2 * jj][1] = r1; bh[2 * jj + 1][0] = r2; bh[2 * jj + 1][1] = r3;
            }
            #pragma unroll
            for (int i = 0; i < 4; i++)
                #pragma unroll
                for (int j = 0; j < 4; j++) mma_f32(acc[i][j], ah[i], bh[j]);
        }
    }
    CP_WAIT0();

    // ---------------- epilogue ----------------
    const int r = lane >> 2, cq = (lane & 3) * 2;

    if (mode == 2) {
        // stage tile in smem, then coalesced transposed store [b][n][s]
        __syncthreads();
        __half* sh = reinterpret_cast<__half*>(smem);   // 128 x 136 fp16
        #pragma unroll
        for (int i = 0; i < 4; i++)
            #pragma unroll
            for (int j = 0; j < 4; j++) {
                const int cl = wn + j * 8 + cq;
                #pragma unroll
                for (int h = 0; h < 2; h++) {
                    const int row = wm + i * 16 + r + h * 8;
                    float v0 = acc[i][j][2 * h + 0] * alpha;
                    float v1 = acc[i][j][2 * h + 1] * alpha;
                    if (bias) { v0 += __ldg(bias + n0 + cl); v1 += __ldg(bias + n0 + cl + 1); }
                    sh[row * 136 + cl]     = __float2half_rn(v0);
                    sh[row * 136 + cl + 1] = __float2half_rn(v1);
                }
            }
        __syncthreads();
        const int c = tid >> 1, half_ = tid & 1;
        const long bidx = (long)(m0 >> 11);
        const int sbase = (m0 & 2047) + half_ * 64;
        const long obase = bidx * E_ * S_ + (long)(n0 + c) * S_ + sbase;
        #pragma unroll
        for (int mm = 0; mm < 64; mm += 8) {
            const int m = half_ * 64 + mm;
            unsigned short uh[8];
            #pragma unroll
            for (int t = 0; t < 8; t++)
                uh[t] = __half_as_ushort(sh[(m + t) * 136 + c]);
            *reinterpret_cast<ushort4*>(Oh + obase + mm)     = make_ushort4(uh[0], uh[1], uh[2], uh[3]);
            *reinterpret_cast<ushort4*>(Oh + obase + mm + 4) = make_ushort4(uh[4], uh[5], uh[6], uh[7]);
        }
        return;
    }

    #pragma unroll
    for (int i = 0; i < 4; i++)
        #pragma unroll
        for (int j = 0; j < 4; j++) {
            const int gn = n0 + wn + j * 8 + cq;
            float bv0 = 0.f, bv1 = 0.f;
            if (bias) { bv0 = __ldg(bias + gn); bv1 = __ldg(bias + gn + 1); }
            #pragma unroll
            for (int h = 0; h < 2; h++) {
                const long gm = m0 + wm + i * 16 + r + h * 8;
                float v0 = acc[i][j][2 * h + 0] * alpha + bv0;
                float v1 = acc[i][j][2 * h + 1] * alpha + bv1;
                if (mode == 3) {
                    *reinterpret_cast<float2*>(Cf + z * sC + gm * Ndim + gn) = make_float2(v0, v1);
                } else {
                    *reinterpret_cast<ushort2*>(Oh + gm * Ndim + gn) =
                        make_ushort2(__half_as_ushort(__float2half_rn(v0)),
                                     __half_as_ushort(__float2half_rn(v1)));
                }
            }
        }
}

// ---------------- fused fp32 -> fp16 conversion (x + 3 weights) ----------------
#define XBLK (MQ*E_/1024)     // 8192 blocks for x
#define WBLK (E_*E_/1024)     // 1024 blocks per weight
__global__ __launch_bounds__(256)
void conv_all(const float* __restrict__ x,  __half* __restrict__ xh,
              const float* __restrict__ w0, const float* __restrict__ w1,
              const float* __restrict__ w2, __half* __restrict__ wh)
{
    const float* s;
    __half* d;
    long base;
    int b = blockIdx.x;
    if (b < XBLK)            { s = x;  d = xh;                         base = (long)b * 1024; }
    else if (b < XBLK+WBLK)  { s = w0; d = wh;                         base = (long)(b - XBLK) * 1024; }
    else if (b < XBLK+2*WBLK){ s = w1; d = wh + (long)E_*E_;           base = (long)(b - XBLK - WBLK) * 1024; }
    else                     { s = w2; d = wh + 2L*E_*E_;              base = (long)(b - XBLK - 2*WBLK) * 1024; }
    long i = base + threadIdx.x * 4;
    float4 v = *reinterpret_cast<const float4*>(s + i);
    *reinterpret_cast<ushort4*>(d + i) = make_ushort4(
        __half_as_ushort(__float2half_rn(v.x)), __half_as_ushort(__float2half_rn(v.y)),
        __half_as_ushort(__float2half_rn(v.z)), __half_as_ushort(__float2half_rn(v.w)));
}

// ---------------- softmax -> fp16 ----------------
__global__ __launch_bounds__(256)
void softmax_f16(const float* __restrict__ P, __half* __restrict__ Ph)
{
    const long row = blockIdx.x;
    const float* p = P + row * (long)S_;
    const int tid = threadIdx.x;

    float v[8];
    float mx = -INFINITY;
    #pragma unroll
    for (int c = 0; c < 8; c += 4) {
        float4 t = *reinterpret_cast<const float4*>(p + tid * 8 + c);
        v[c] = t.x; v[c+1] = t.y; v[c+2] = t.z; v[c+3] = t.w;
        mx = fmaxf(mx, fmaxf(fmaxf(t.x, t.y), fmaxf(t.z, t.w)));
    }
    __shared__ float red[8];
    #pragma unroll
    for (int o = 16; o > 0; o >>= 1) mx = fmaxf(mx, __shfl_xor_sync(0xffffffffu, mx, o));
    if ((tid & 31) == 0) red[tid >> 5] = mx;
    __syncthreads();
    float zm = red[0];
    #pragma unroll
    for (int i = 1; i < 8; i++) zm = fmaxf(zm, red[i]);
    __syncthreads();

    float sm = 0.f;
    #pragma unroll
    for (int i = 0; i < 8; i++) { v[i] = __expf(v[i] - zm); sm += v[i]; }
    #pragma unroll
    for (int o = 16; o > 0; o >>= 1) sm += __shfl_xor_sync(0xffffffffu, sm, o);
    if ((tid & 31) == 0) red[tid >> 5] = sm;
    __syncthreads();
    float tot = 0.f;
    #pragma unroll
    for (int i = 0; i < 8; i++) tot += red[i];
    const float inv = 1.f / tot;

    #pragma unroll
    for (int c = 0; c < 8; c += 4) {
        ushort4 o;
        o.x = __half_as_ushort(__float2half_rn(v[c + 0] * inv));
        o.y = __half_as_ushort(__float2half_rn(v[c + 1] * inv));
        o.z = __half_as_ushort(__float2half_rn(v[c + 2] * inv));
        o.w = __half_as_ushort(__float2half_rn(v[c + 3] * inv));
        *reinterpret_cast<ushort4*>(Ph + row * (long)S_ + tid * 8 + c) = o;
    }
}

// ---------------- launch ----------------
extern "C" void kernel_launch(void* const* d_in, const int* in_sizes, int n_in,
                              void* d_out, int out_size)
{
    const float* x  = (const float*)d_in[0];
    const float* wq = (const float*)d_in[1];
    const float* bq = (const float*)d_in[2];
    const float* wk = (const float*)d_in[3];
    const float* bk = (const float*)d_in[4];
    const float* wv = (const float*)d_in[5];
    const float* bv = (const float*)d_in[6];
    float* out = (float*)d_out;

    __half *xh, *wh, *Qh, *Kh, *Vh, *Ph;
    float* P;
    cudaGetSymbolAddress((void**)&xh, g_xh);
    cudaGetSymbolAddress((void**)&wh, g_wh);
    cudaGetSymbolAddress((void**)&Qh, g_Qh);
    cudaGetSymbolAddress((void**)&Kh, g_Kh);
    cudaGetSymbolAddress((void**)&Vh, g_Vh);
    cudaGetSymbolAddress((void**)&P,  g_P);
    cudaGetSymbolAddress((void**)&Ph, g_Ph);

    cudaFuncSetAttribute(gemm_f16, cudaFuncAttributeMaxDynamicSharedMemorySize, SMEM_SZ);

    const long nw = (long)E_ * E_;

    // fused fp32->fp16 conversion (x + wq + wk + wv)
    conv_all<<<XBLK + 3 * WBLK, 256>>>(x, xh, wq, wk, wv, wh);

    // QKV projections fused: grid.z selects W slice / bias / output; M=8192, N=1024, K=1024
    dim3 g1(E_ / NT, MQ / MT, 3);
    gemm_f16<<<g1, NTH, SMEM_SZ>>>(xh, wh, bq, bk, bv,
                                   nullptr, Qh, Kh, Vh,
                                   E_, E_, 1.f, 0, nw, 0, 4);

    // scores = Q K^T / 32 : per-batch M=N=2048, K=1024
    dim3 g2(S_ / NT, S_ / MT, B_);
    gemm_f16<<<g2, NTH, SMEM_SZ>>>(Qh, Kh, nullptr, nullptr, nullptr,
                                   P, nullptr, nullptr, nullptr,
                                   S_, E_, 0.03125f,
                                   (long)S_ * E_, (long)S_ * E_, (long)S_ * S_, 3);

    softmax_f16<<<B_ * S_, 256>>>(P, Ph);

    // out = P V : per-batch M=2048, N=1024, K=2048 (B = V^T)
    dim3 g3(E_ / NT, S_ / MT, B_);
    gemm_f16<<<g3, NTH, SMEM_SZ>>>(Ph, Vh, nullptr, nullptr, nullptr,
                                   out, nullptr, nullptr, nullptr,
                                   E_, S_, 1.f,
                                   (long)S_ * S_, (long)E_ * S_, (long)S_ * E_, 3);
}